// round 9
// baseline (speedup 1.0000x reference)
#include <cuda_runtime.h>
#include <cuda_bf16.h>
#include <math.h>

#define BS 16
#define Q 900
#define NC 92
#define TPB 100          // targets per batch
#define NT 1600          // total targets
#define C_ELEMS (16*900*1600)  // 23040000
#define ROW_F4 (Q/4)     // 225 float4 per row

// transposed per-batch cost slice, 16B-aligned for float4 loads
__device__ float4 g_ctr4[BS * TPB * ROW_F4];
__device__ int    g_idmode;

// ---------------------------------------------------------------------------
// Side stream + events for fork-join overlap, created at static-init time
// (before the harness's memory checkpoints; no device memory involved).
// ---------------------------------------------------------------------------
static cudaStream_t g_s2 = 0;
static cudaEvent_t  g_e1 = 0, g_e2 = 0;
static bool g_fork_ok = false;
namespace {
struct GInit {
    GInit() {
        g_fork_ok =
            (cudaStreamCreateWithFlags(&g_s2, cudaStreamNonBlocking) == cudaSuccess) &&
            (cudaEventCreateWithFlags(&g_e1, cudaEventDisableTiming) == cudaSuccess) &&
            (cudaEventCreateWithFlags(&g_e2, cudaEventDisableTiming) == cudaSuccess);
    }
};
static GInit g_init;
}

// ---------------------------------------------------------------------------
__global__ void detect_ids_kernel(const unsigned int* __restrict__ ids)
{
    const int tid = threadIdx.x;  // 128
    int ok = 1;
    for (int k = tid; k < 800; k += 128) {
        unsigned lo = ids[2*k], hi = ids[2*k+1];
        if (hi != 0u || lo >= 92u) ok = 0;
    }
    ok = __syncthreads_and(ok);
    if (tid == 0) g_idmode = ok;
}

// ---------------------------------------------------------------------------
// Full cost matrix kernel (writes C only). Runs on the side stream,
// overlapped with the LSA. 8 queries per block, 128 threads.
// ---------------------------------------------------------------------------
#define QPB 8
__global__ void cost_kernel(const float* __restrict__ logits,
                            const float* __restrict__ boxes,
                            const void*  __restrict__ ids,
                            const float* __restrict__ tbox,
                            float* __restrict__ C)
{
    __shared__ float4 s_tb[NT];
    __shared__ int    s_id[NT];
    __shared__ float  s_prob[QPB][NC];
    __shared__ float  s_box[QPB][4];

    const int tid = threadIdx.x;         // 128
    const int base_bq = blockIdx.x * QPB;
    const int mode = g_idmode;

    const float4* tb4 = (const float4*)tbox;
    for (int x = tid; x < NT; x += 128) s_tb[x] = tb4[x];
    if (mode) {
        const long long* id64 = (const long long*)ids;
        for (int x = tid; x < NT; x += 128) s_id[x] = (int)id64[x];
    } else {
        const int* id32 = (const int*)ids;
        for (int x = tid; x < NT; x += 128) s_id[x] = id32[x];
    }

    const int w = tid >> 5, lane = tid & 31;
    for (int r = w; r < QPB; r += 4) {
        int bq = base_bq + r;
        const float* lr = logits + (size_t)bq * NC;
        float x0 = lr[lane];
        float x1 = lr[lane + 32];
        float x2 = (lane + 64 < NC) ? lr[lane + 64] : -1e30f;
        float m = fmaxf(x0, fmaxf(x1, x2));
        for (int o = 16; o; o >>= 1) m = fmaxf(m, __shfl_xor_sync(~0u, m, o));
        float e0 = expf(x0 - m);
        float e1 = expf(x1 - m);
        float e2 = (lane + 64 < NC) ? expf(x2 - m) : 0.0f;
        float s = e0 + e1 + e2;
        for (int o = 16; o; o >>= 1) s += __shfl_xor_sync(~0u, s, o);
        float inv = 1.0f / s;
        s_prob[r][lane]      = e0 * inv;
        s_prob[r][lane + 32] = e1 * inv;
        if (lane + 64 < NC) s_prob[r][lane + 64] = e2 * inv;
        if (lane < 4) s_box[r][lane] = boxes[(size_t)bq * 4 + lane];
    }
    __syncthreads();

    for (int r = 0; r < QPB; r++) {
        const int bq = base_bq + r;
        const float pcx = s_box[r][0], pcy = s_box[r][1];
        const float pw  = s_box[r][2], ph  = s_box[r][3];
        const float px0 = pcx - pw * 0.5f, py0 = pcy - ph * 0.5f;
        const float px1 = pcx + pw * 0.5f, py1 = pcy + ph * 0.5f;
        const float pa  = (px1 - px0) * (py1 - py0);
        float* Crow = C + (size_t)bq * NT;
        for (int j = tid; j < NT; j += 128) {
            float4 t = s_tb[j];
            float tx0 = t.x, ty0 = t.y, tx1 = t.z, ty1 = t.w;
            float tcx = (tx0 + tx1) * 0.5f, tcy = (ty0 + ty1) * 0.5f;
            float tw = tx1 - tx0, th = ty1 - ty0;
            float cbb = fabsf(pcx - tcx) + fabsf(pcy - tcy)
                      + fabsf(pw - tw) + fabsf(ph - th);
            float ta = tw * th;
            float ix0 = fmaxf(px0, tx0), iy0 = fmaxf(py0, ty0);
            float ix1 = fminf(px1, tx1), iy1 = fminf(py1, ty1);
            float iw = fmaxf(ix1 - ix0, 0.0f), ih = fmaxf(iy1 - iy0, 0.0f);
            float inter = iw * ih;
            float uni = pa + ta - inter;
            float iou = inter / uni;
            float ex0 = fminf(px0, tx0), ey0 = fminf(py0, ty0);
            float ex1 = fmaxf(px1, tx1), ey1 = fmaxf(py1, ty1);
            float cw = fmaxf(ex1 - ex0, 0.0f), ch = fmaxf(ey1 - ey0, 0.0f);
            float ca = cw * ch;
            float giou = iou - (ca - uni) / ca;
            float val = 5.0f * cbb - s_prob[r][s_id[j]] - 2.0f * giou;
            Crow[j] = val;
        }
    }
}

// ---------------------------------------------------------------------------
// Slice kernel: computes ONLY the per-batch slice, directly transposed into
// g_ctr[b][t][q]. Same softmax butterfly + same per-element op order as
// cost_kernel. Block = 96 threads = 96 queries of one batch.
// ---------------------------------------------------------------------------
#define SQ 96
__global__ void slice_kernel(const float* __restrict__ logits,
                             const float* __restrict__ boxes,
                             const void*  __restrict__ ids,
                             const float* __restrict__ tbox)
{
    __shared__ float  s_prob[SQ][NC];
    __shared__ float4 s_tb[TPB];
    __shared__ int    s_id[TPB];
    __shared__ float4 s_box[SQ];

    const int b   = blockIdx.y;
    const int q0  = blockIdx.x * SQ;
    const int tid = threadIdx.x;           // 96
    const int w = tid >> 5, lane = tid & 31;
    const int mode = g_idmode;

    // stage this batch's targets
    const float4* tb4 = (const float4*)tbox;
    for (int x = tid; x < TPB; x += SQ) s_tb[x] = tb4[b * TPB + x];
    if (mode) {
        const long long* id64 = (const long long*)ids;
        for (int x = tid; x < TPB; x += SQ) s_id[x] = (int)id64[b * TPB + x];
    } else {
        const int* id32 = (const int*)ids;
        for (int x = tid; x < TPB; x += SQ) s_id[x] = id32[b * TPB + x];
    }
    // stage pred boxes
    {
        int q = q0 + tid;
        if (q < Q) s_box[tid] = ((const float4*)boxes)[(size_t)b * Q + q];
    }

    // softmax: warp w handles local queries [w*32, w*32+32)
    for (int r2 = 0; r2 < 32; r2++) {
        int ql = w * 32 + r2;
        int q = q0 + ql;
        if (q >= Q) break;
        const float* lr = logits + ((size_t)(b * Q + q)) * NC;
        float x0 = lr[lane];
        float x1 = lr[lane + 32];
        float x2 = (lane + 64 < NC) ? lr[lane + 64] : -1e30f;
        float m = fmaxf(x0, fmaxf(x1, x2));
        for (int o = 16; o; o >>= 1) m = fmaxf(m, __shfl_xor_sync(~0u, m, o));
        float e0 = expf(x0 - m);
        float e1 = expf(x1 - m);
        float e2 = (lane + 64 < NC) ? expf(x2 - m) : 0.0f;
        float s = e0 + e1 + e2;
        for (int o = 16; o; o >>= 1) s += __shfl_xor_sync(~0u, s, o);
        float inv = 1.0f / s;
        s_prob[ql][lane]      = e0 * inv;
        s_prob[ql][lane + 32] = e1 * inv;
        if (lane + 64 < NC) s_prob[ql][lane + 64] = e2 * inv;
    }
    __syncthreads();

    const int q = q0 + tid;
    if (q >= Q) return;
    float* g_ctrf = (float*)g_ctr4;

    const float4 pb = s_box[tid];
    const float pcx = pb.x, pcy = pb.y, pw = pb.z, ph = pb.w;
    const float px0 = pcx - pw * 0.5f, py0 = pcy - ph * 0.5f;
    const float px1 = pcx + pw * 0.5f, py1 = pcy + ph * 0.5f;
    const float pa  = (px1 - px0) * (py1 - py0);

    for (int t = 0; t < TPB; t++) {
        float4 tt = s_tb[t];
        float tx0 = tt.x, ty0 = tt.y, tx1 = tt.z, ty1 = tt.w;
        float tcx = (tx0 + tx1) * 0.5f, tcy = (ty0 + ty1) * 0.5f;
        float tw = tx1 - tx0, th = ty1 - ty0;
        float cbb = fabsf(pcx - tcx) + fabsf(pcy - tcy)
                  + fabsf(pw - tw) + fabsf(ph - th);
        float ta = tw * th;
        float ix0 = fmaxf(px0, tx0), iy0 = fmaxf(py0, ty0);
        float ix1 = fminf(px1, tx1), iy1 = fminf(py1, ty1);
        float iw = fmaxf(ix1 - ix0, 0.0f), ih = fmaxf(iy1 - iy0, 0.0f);
        float inter = iw * ih;
        float uni = pa + ta - inter;
        float iou = inter / uni;
        float ex0 = fminf(px0, tx0), ey0 = fminf(py0, ty0);
        float ex1 = fmaxf(px1, tx1), ey1 = fmaxf(py1, ty1);
        float cw = fmaxf(ex1 - ex0, 0.0f), ch = fmaxf(ey1 - ey0, 0.0f);
        float ca = cw * ch;
        float giou = iou - (ca - uni) / ca;
        float val = 5.0f * cbb - s_prob[tid][s_id[t]] - 2.0f * giou;
        g_ctrf[b * (TPB * Q) + t * Q + q] = val;
    }
}

// ---------------------------------------------------------------------------
// Order-preserving double <-> uint64 encoding (ascending). -0 canonicalization
// omitted (RN subtractions here cannot produce -0).
// ---------------------------------------------------------------------------
__device__ __forceinline__ unsigned long long enc64(double x)
{
    long long b = __double_as_longlong(x);
    return (unsigned long long)(b ^ ((b >> 63) | 0x8000000000000000LL));
}
__device__ __forceinline__ double dec64(unsigned long long e)
{
    long long b = (long long)e;
    b ^= ((~b) >> 63) | 0x8000000000000000LL;
    return __longlong_as_double(b);
}

// ---------------------------------------------------------------------------
// Hungarian (JV), one block of 128 threads per batch (unchanged from R8).
// ---------------------------------------------------------------------------
__global__ void __launch_bounds__(128, 1) lsa_kernel(float* __restrict__ out)
{
    const int b = blockIdx.x;
    const int tid = threadIdx.x;
    const int w = tid >> 5, lane = tid & 31;
    const bool g1ok = (tid < 97);

    __shared__ double u[TPB + 2];
    __shared__ int    p[Q + 2];
    __shared__ int    way[Q + 2];
    __shared__ unsigned long long s_em[2][4];
    __shared__ int    s_j[2][4];
    __shared__ int    s_p[2][4];
    __shared__ int    ans[TPB];

    double v[8];
    int rowof[8];
    int colv[8];
#pragma unroll
    for (int k = 0; k < 8; k++) {
        v[k] = 0.0; rowof[k] = 0;
        colv[k] = (k < 4) ? (4 * tid + k) : (512 + 4 * tid + (k - 4));
    }

    for (int x = tid; x <= Q; x += 128) p[x] = 0;
    if (tid <= TPB) u[tid] = 0.0;
    __syncthreads();

    const float4* cb4 = g_ctr4 + b * (TPB * ROW_F4);

    float4 nxt0 = __ldg(&cb4[tid]);
    float4 nxt1 = g1ok ? __ldg(&cb4[128 + tid]) : make_float4(0.f,0.f,0.f,0.f);

    int par = 0;

    for (int i = 1; i <= TPB; i++) {
        if (tid == 0) p[0] = i;
        double minv[8];
        unsigned long long em[8];
        unsigned usedm = 0;

        float rwf[8] = { nxt0.x, nxt0.y, nxt0.z, nxt0.w,
                         nxt1.x, nxt1.y, nxt1.z, nxt1.w };
        unsigned long long bestE = ~0ULL; int bestJ = Q + 2;
#pragma unroll
        for (int k = 0; k < 8; k++) {
            if (k < 4 || g1ok) {
                double cur = ((double)rwf[k] - 0.0) - v[k];
                minv[k] = cur; em[k] = enc64(cur); way[colv[k] + 1] = 0;
                if (em[k] < bestE) { bestE = em[k]; bestJ = colv[k] + 1; }
            } else { minv[k] = 1e300; em[k] = ~0ULL; }
        }

        if (i < TPB) {
            nxt0 = __ldg(&cb4[i * ROW_F4 + tid]);
            if (g1ok) nxt1 = __ldg(&cb4[i * ROW_F4 + 128 + tid]);
        }

        while (true) {
            unsigned hi  = (unsigned)(bestE >> 32);
            unsigned mhi = __reduce_min_sync(0xffffffffu, hi);
            unsigned bal = __ballot_sync(0xffffffffu, hi == mhi);
            int srcJ;
            if (__popc(bal) == 1) {
                int src = __ffs(bal) - 1;
                if (lane == src) { s_em[par][w] = bestE; s_j[par][w] = bestJ; }
                srcJ = __shfl_sync(0xffffffffu, bestJ, src);
            } else {
                unsigned lo  = (hi == mhi) ? (unsigned)bestE : 0xffffffffu;
                unsigned mlo = __reduce_min_sync(0xffffffffu, lo);
                unsigned cjj = (hi == mhi && (unsigned)bestE == mlo)
                               ? (unsigned)bestJ : 0x7fffffffu;
                unsigned mj  = __reduce_min_sync(0xffffffffu, cjj);
                if ((unsigned)bestJ == mj) {
                    s_em[par][w] = ((unsigned long long)mhi << 32) | mlo;
                    s_j[par][w]  = mj;
                }
                srcJ = (int)mj;
            }
            const int wp = p[srcJ];
            if (lane == 0) s_p[par][w] = wp;

            float4 own0, own1;
            own0 = make_float4(0.f,0.f,0.f,0.f); own1 = own0;
            if (wp) {
                const float4* cr = cb4 + (wp - 1) * ROW_F4;
                own0 = __ldg(&cr[tid]);
                if (g1ok) own1 = __ldg(&cr[128 + tid]);
            }
            __syncthreads();                                   // ONE barrier

            unsigned long long ce0 = s_em[par][0], ce1 = s_em[par][1],
                               ce2 = s_em[par][2], ce3 = s_em[par][3];
            int cj0 = s_j[par][0], cj1 = s_j[par][1],
                cj2 = s_j[par][2], cj3 = s_j[par][3];
            int cp0 = s_p[par][0], cp1 = s_p[par][1],
                cp2 = s_p[par][2], cp3 = s_p[par][3];

            float4 ra0, rb0, ra1, rb1, ra2, rb2, ra3, rb3;
            if (w == 0) { ra0 = own0; rb0 = own1; }
            else if (cp0) { const float4* cr = cb4 + (cp0 - 1) * ROW_F4;
                ra0 = __ldg(&cr[tid]); if (g1ok) rb0 = __ldg(&cr[128 + tid]); }
            if (w == 1) { ra1 = own0; rb1 = own1; }
            else if (cp1) { const float4* cr = cb4 + (cp1 - 1) * ROW_F4;
                ra1 = __ldg(&cr[tid]); if (g1ok) rb1 = __ldg(&cr[128 + tid]); }
            if (w == 2) { ra2 = own0; rb2 = own1; }
            else if (cp2) { const float4* cr = cb4 + (cp2 - 1) * ROW_F4;
                ra2 = __ldg(&cr[tid]); if (g1ok) rb2 = __ldg(&cr[128 + tid]); }
            if (w == 3) { ra3 = own0; rb3 = own1; }
            else if (cp3) { const float4* cr = cb4 + (cp3 - 1) * ROW_F4;
                ra3 = __ldg(&cr[tid]); if (g1ok) rb3 = __ldg(&cr[128 + tid]); }

            unsigned long long de = ce0; int j1 = cj0, i1 = cp0, ww = 0;
            if (ce1 < de || (ce1 == de && cj1 < j1)) { de = ce1; j1 = cj1; i1 = cp1; ww = 1; }
            if (ce2 < de || (ce2 == de && cj2 < j1)) { de = ce2; j1 = cj2; i1 = cp2; ww = 2; }
            if (ce3 < de || (ce3 == de && cj3 < j1)) { de = ce3; j1 = cj3; i1 = cp3; ww = 3; }
            const double delta = dec64(de);

            if (i1 == 0) {
#pragma unroll
                for (int k = 0; k < 8; k++) {
                    if ((k < 4 || g1ok) && ((usedm >> k) & 1u)) {
                        v[k] -= delta; u[rowof[k]] += delta;
                    }
                }
                if (tid == 0) {
                    u[i] += delta;
                    int jj = j1;
                    while (jj) { int jp = way[jj]; p[jj] = p[jp]; jj = jp; }
                }
                par ^= 1;
                break;
            }

            const double ui1 = u[i1];

            float4 wa = ra0, wb = rb0;
            if (ww == 1) { wa = ra1; wb = rb1; }
            if (ww == 2) { wa = ra2; wb = rb2; }
            if (ww == 3) { wa = ra3; wb = rb3; }
            rwf[0] = wa.x; rwf[1] = wa.y; rwf[2] = wa.z; rwf[3] = wa.w;
            rwf[4] = wb.x; rwf[5] = wb.y; rwf[6] = wb.z; rwf[7] = wb.w;

            bestE = ~0ULL; bestJ = Q + 2;
#pragma unroll
            for (int k = 0; k < 8; k++) {
                if (k < 4 || g1ok) {
                    if ((usedm >> k) & 1u) {
                        v[k] -= delta; u[rowof[k]] += delta;
                    } else if (colv[k] + 1 != j1) {
                        double m2  = minv[k] - delta;
                        double cur = ((double)rwf[k] - ui1) - v[k];
                        unsigned long long e2 = enc64(m2);
                        unsigned long long ec = enc64(cur);
                        if (ec < e2) { minv[k] = cur; em[k] = ec; way[colv[k] + 1] = j1; }
                        else         { minv[k] = m2;  em[k] = e2; }
                        if (em[k] < bestE) { bestE = em[k]; bestJ = colv[k] + 1; }
                    }
                }
            }
            if (tid == 0) u[i] += delta;

            {
                int c = j1 - 1, og, okk;
                if (c < 512) { og = c >> 2;        okk = c & 3; }
                else         { og = (c - 512) >> 2; okk = 4 + ((c - 512) & 3); }
                if (og == tid) { usedm |= 1u << okk; rowof[okk] = i1; }
            }
            par ^= 1;
        }
        __syncthreads();
    }

#pragma unroll
    for (int k = 0; k < 8; k++) {
        if (k < 4 || g1ok) {
            int j = colv[k] + 1;
            if (p[j] > 0) ans[p[j] - 1] = j - 1;
        }
    }
    __syncthreads();
    if (tid < TPB) {
        int a = ans[tid];
        int rank = 0;
        for (int t2 = 0; t2 < TPB; t2++) rank += (ans[t2] < a) ? 1 : 0;
        out[(size_t)C_ELEMS + (size_t)b * TPB + rank]                    = (float)a;
        out[(size_t)C_ELEMS + (size_t)BS * TPB + (size_t)b * TPB + rank] = (float)tid;
    }
}

// ---------------------------------------------------------------------------
extern "C" void kernel_launch(void* const* d_in, const int* in_sizes, int n_in,
                              void* d_out, int out_size)
{
    const float* logits = (const float*)d_in[0];
    const float* boxes  = (const float*)d_in[1];
    const void*  ids    = d_in[2];
    const float* tbox   = (const float*)d_in[3];
    float* out = (float*)d_out;

    dim3 sgrid((Q + SQ - 1) / SQ, BS);

    if (g_fork_ok) {
        // main stream: detect -> slice -> lsa   (critical path)
        // side stream: cost_kernel (92MB C write), overlapped with lsa
        detect_ids_kernel<<<1, 128>>>((const unsigned int*)ids);
        cudaEventRecord(g_e1, 0);
        cudaStreamWaitEvent(g_s2, g_e1, 0);
        cost_kernel<<<(BS * Q) / QPB, 128, 0, g_s2>>>(logits, boxes, ids, tbox, out);
        slice_kernel<<<sgrid, SQ>>>(logits, boxes, ids, tbox);
        lsa_kernel<<<BS, 128>>>(out);
        cudaEventRecord(g_e2, g_s2);
        cudaStreamWaitEvent(0, g_e2, 0);
    } else {
        detect_ids_kernel<<<1, 128>>>((const unsigned int*)ids);
        slice_kernel<<<sgrid, SQ>>>(logits, boxes, ids, tbox);
        cost_kernel<<<(BS * Q) / QPB, 128>>>(logits, boxes, ids, tbox, out);
        lsa_kernel<<<BS, 128>>>(out);
    }
}

// round 10
// speedup vs baseline: 1.3609x; 1.3609x over previous
#include <cuda_runtime.h>
#include <cuda_bf16.h>
#include <math.h>

#define BS 16
#define Q 900
#define NC 92
#define TPB 100          // targets per batch
#define NT 1600          // total targets
#define C_ELEMS (16*900*1600)  // 23040000
#define ROW_F4 (Q/4)     // 225 float4 per row
#define QPB 8

// transposed per-batch cost slice, 16B-aligned for float4 loads
__device__ float4 g_ctr4[BS * TPB * ROW_F4];
__device__ int    g_idmode;

// ---------------------------------------------------------------------------
__global__ void detect_ids_kernel(const unsigned int* __restrict__ ids)
{
    const int tid = threadIdx.x;  // 128
    int ok = 1;
    for (int k = tid; k < 800; k += 128) {
        unsigned lo = ids[2*k], hi = ids[2*k+1];
        if (hi != 0u || lo >= 92u) ok = 0;
    }
    ok = __syncthreads_and(ok);
    if (tid == 0) g_idmode = ok;
}

// ---------------------------------------------------------------------------
// Slice kernel: per-batch slice, transposed into g_ctr[b][t][q].
// 8 queries/block, 128 threads, warp-parallel softmax (cost-kernel shape).
// Same per-element fp op order as the cost path.
// ---------------------------------------------------------------------------
__global__ void __launch_bounds__(128) slice_kernel(
    const float* __restrict__ logits,
    const float* __restrict__ boxes,
    const void*  __restrict__ ids,
    const float* __restrict__ tbox)
{
    __shared__ float4 s_tb[TPB];
    __shared__ int    s_id[TPB];
    __shared__ float  s_prob[QPB][NC];
    __shared__ float  s_box[QPB][4];
    __shared__ float  s_out[TPB][QPB];

    const int b   = blockIdx.y;
    const int q0  = blockIdx.x * QPB;
    const int tid = threadIdx.x;           // 128
    const int w = tid >> 5, lane = tid & 31;
    const int mode = g_idmode;

    const float4* tb4 = (const float4*)tbox;
    if (tid < TPB) s_tb[tid] = tb4[b * TPB + tid];
    if (mode) {
        const long long* id64 = (const long long*)ids;
        if (tid < TPB) s_id[tid] = (int)id64[b * TPB + tid];
    } else {
        const int* id32 = (const int*)ids;
        if (tid < TPB) s_id[tid] = id32[b * TPB + tid];
    }

    for (int r = w; r < QPB; r += 4) {
        int q = q0 + r;
        if (q >= Q) break;
        const float* lr = logits + ((size_t)(b * Q + q)) * NC;
        float x0 = lr[lane];
        float x1 = lr[lane + 32];
        float x2 = (lane + 64 < NC) ? lr[lane + 64] : -1e30f;
        float m = fmaxf(x0, fmaxf(x1, x2));
        for (int o = 16; o; o >>= 1) m = fmaxf(m, __shfl_xor_sync(~0u, m, o));
        float e0 = expf(x0 - m);
        float e1 = expf(x1 - m);
        float e2 = (lane + 64 < NC) ? expf(x2 - m) : 0.0f;
        float s = e0 + e1 + e2;
        for (int o = 16; o; o >>= 1) s += __shfl_xor_sync(~0u, s, o);
        float inv = 1.0f / s;
        s_prob[r][lane]      = e0 * inv;
        s_prob[r][lane + 32] = e1 * inv;
        if (lane + 64 < NC) s_prob[r][lane + 64] = e2 * inv;
        if (lane < 4) s_box[r][lane] = boxes[((size_t)(b * Q + q)) * 4 + lane];
    }
    __syncthreads();

    for (int r = 0; r < QPB; r++) {
        int q = q0 + r;
        if (q >= Q) break;
        const float pcx = s_box[r][0], pcy = s_box[r][1];
        const float pw  = s_box[r][2], ph  = s_box[r][3];
        const float px0 = pcx - pw * 0.5f, py0 = pcy - ph * 0.5f;
        const float px1 = pcx + pw * 0.5f, py1 = pcy + ph * 0.5f;
        const float pa  = (px1 - px0) * (py1 - py0);
        if (tid < TPB) {
            float4 t = s_tb[tid];
            float tx0 = t.x, ty0 = t.y, tx1 = t.z, ty1 = t.w;
            float tcx = (tx0 + tx1) * 0.5f, tcy = (ty0 + ty1) * 0.5f;
            float tw = tx1 - tx0, th = ty1 - ty0;
            float cbb = fabsf(pcx - tcx) + fabsf(pcy - tcy)
                      + fabsf(pw - tw) + fabsf(ph - th);
            float ta = tw * th;
            float ix0 = fmaxf(px0, tx0), iy0 = fmaxf(py0, ty0);
            float ix1 = fminf(px1, tx1), iy1 = fminf(py1, ty1);
            float iw = fmaxf(ix1 - ix0, 0.0f), ih = fmaxf(iy1 - iy0, 0.0f);
            float inter = iw * ih;
            float uni = pa + ta - inter;
            float iou = inter / uni;
            float ex0 = fminf(px0, tx0), ey0 = fminf(py0, ty0);
            float ex1 = fmaxf(px1, tx1), ey1 = fmaxf(py1, ty1);
            float cw = fmaxf(ex1 - ex0, 0.0f), ch = fmaxf(ey1 - ey0, 0.0f);
            float ca = cw * ch;
            float giou = iou - (ca - uni) / ca;
            s_out[tid][r] = 5.0f * cbb - s_prob[r][s_id[tid]] - 2.0f * giou;
        }
    }
    __syncthreads();

    // coalesced-ish writes: 8 consecutive floats (one 32B sector) per t
    float* g_ctrf = (float*)g_ctr4;
    for (int idx = tid; idx < TPB * QPB; idx += 128) {
        int t = idx >> 3, r = idx & 7;
        int q = q0 + r;
        if (q < Q)
            g_ctrf[b * (TPB * Q) + t * Q + q] = s_out[t][r];
    }
}

// ---------------------------------------------------------------------------
// Order-preserving double <-> uint64 encoding (ascending). -0 canonicalization
// omitted (RN subtractions here cannot produce -0).
// ---------------------------------------------------------------------------
__device__ __forceinline__ unsigned long long enc64(double x)
{
    long long b = __double_as_longlong(x);
    return (unsigned long long)(b ^ ((b >> 63) | 0x8000000000000000LL));
}
__device__ __forceinline__ double dec64(unsigned long long e)
{
    long long b = (long long)e;
    b ^= ((~b) >> 63) | 0x8000000000000000LL;
    return __longlong_as_double(b);
}

// ---------------------------------------------------------------------------
// LSA device function (R8 logic, unchanged). One block of 128 threads.
// ---------------------------------------------------------------------------
__device__ __noinline__ void lsa_block(int b, float* __restrict__ out)
{
    const int tid = threadIdx.x;
    const int w = tid >> 5, lane = tid & 31;
    const bool g1ok = (tid < 97);

    __shared__ double u[TPB + 2];
    __shared__ int    p[Q + 2];
    __shared__ int    way[Q + 2];
    __shared__ unsigned long long s_em[2][4];
    __shared__ int    s_j[2][4];
    __shared__ int    s_p[2][4];
    __shared__ int    ans[TPB];

    double v[8];
    int rowof[8];
    int colv[8];
#pragma unroll
    for (int k = 0; k < 8; k++) {
        v[k] = 0.0; rowof[k] = 0;
        colv[k] = (k < 4) ? (4 * tid + k) : (512 + 4 * tid + (k - 4));
    }

    for (int x = tid; x <= Q; x += 128) p[x] = 0;
    if (tid <= TPB) u[tid] = 0.0;
    __syncthreads();

    const float4* cb4 = g_ctr4 + b * (TPB * ROW_F4);

    float4 nxt0 = __ldg(&cb4[tid]);
    float4 nxt1 = g1ok ? __ldg(&cb4[128 + tid]) : make_float4(0.f,0.f,0.f,0.f);

    int par = 0;

    for (int i = 1; i <= TPB; i++) {
        if (tid == 0) p[0] = i;
        double minv[8];
        unsigned long long em[8];
        unsigned usedm = 0;

        float rwf[8] = { nxt0.x, nxt0.y, nxt0.z, nxt0.w,
                         nxt1.x, nxt1.y, nxt1.z, nxt1.w };
        unsigned long long bestE = ~0ULL; int bestJ = Q + 2;
#pragma unroll
        for (int k = 0; k < 8; k++) {
            if (k < 4 || g1ok) {
                double cur = ((double)rwf[k] - 0.0) - v[k];
                minv[k] = cur; em[k] = enc64(cur); way[colv[k] + 1] = 0;
                if (em[k] < bestE) { bestE = em[k]; bestJ = colv[k] + 1; }
            } else { minv[k] = 1e300; em[k] = ~0ULL; }
        }

        if (i < TPB) {
            nxt0 = __ldg(&cb4[i * ROW_F4 + tid]);
            if (g1ok) nxt1 = __ldg(&cb4[i * ROW_F4 + 128 + tid]);
        }

        while (true) {
            unsigned hi  = (unsigned)(bestE >> 32);
            unsigned mhi = __reduce_min_sync(0xffffffffu, hi);
            unsigned bal = __ballot_sync(0xffffffffu, hi == mhi);
            int srcJ;
            if (__popc(bal) == 1) {
                int src = __ffs(bal) - 1;
                if (lane == src) { s_em[par][w] = bestE; s_j[par][w] = bestJ; }
                srcJ = __shfl_sync(0xffffffffu, bestJ, src);
            } else {
                unsigned lo  = (hi == mhi) ? (unsigned)bestE : 0xffffffffu;
                unsigned mlo = __reduce_min_sync(0xffffffffu, lo);
                unsigned cjj = (hi == mhi && (unsigned)bestE == mlo)
                               ? (unsigned)bestJ : 0x7fffffffu;
                unsigned mj  = __reduce_min_sync(0xffffffffu, cjj);
                if ((unsigned)bestJ == mj) {
                    s_em[par][w] = ((unsigned long long)mhi << 32) | mlo;
                    s_j[par][w]  = mj;
                }
                srcJ = (int)mj;
            }
            const int wp = p[srcJ];
            if (lane == 0) s_p[par][w] = wp;

            float4 own0, own1;
            own0 = make_float4(0.f,0.f,0.f,0.f); own1 = own0;
            if (wp) {
                const float4* cr = cb4 + (wp - 1) * ROW_F4;
                own0 = __ldg(&cr[tid]);
                if (g1ok) own1 = __ldg(&cr[128 + tid]);
            }
            __syncthreads();                                   // ONE barrier

            unsigned long long ce0 = s_em[par][0], ce1 = s_em[par][1],
                               ce2 = s_em[par][2], ce3 = s_em[par][3];
            int cj0 = s_j[par][0], cj1 = s_j[par][1],
                cj2 = s_j[par][2], cj3 = s_j[par][3];
            int cp0 = s_p[par][0], cp1 = s_p[par][1],
                cp2 = s_p[par][2], cp3 = s_p[par][3];

            float4 ra0, rb0, ra1, rb1, ra2, rb2, ra3, rb3;
            if (w == 0) { ra0 = own0; rb0 = own1; }
            else if (cp0) { const float4* cr = cb4 + (cp0 - 1) * ROW_F4;
                ra0 = __ldg(&cr[tid]); if (g1ok) rb0 = __ldg(&cr[128 + tid]); }
            if (w == 1) { ra1 = own0; rb1 = own1; }
            else if (cp1) { const float4* cr = cb4 + (cp1 - 1) * ROW_F4;
                ra1 = __ldg(&cr[tid]); if (g1ok) rb1 = __ldg(&cr[128 + tid]); }
            if (w == 2) { ra2 = own0; rb2 = own1; }
            else if (cp2) { const float4* cr = cb4 + (cp2 - 1) * ROW_F4;
                ra2 = __ldg(&cr[tid]); if (g1ok) rb2 = __ldg(&cr[128 + tid]); }
            if (w == 3) { ra3 = own0; rb3 = own1; }
            else if (cp3) { const float4* cr = cb4 + (cp3 - 1) * ROW_F4;
                ra3 = __ldg(&cr[tid]); if (g1ok) rb3 = __ldg(&cr[128 + tid]); }

            unsigned long long de = ce0; int j1 = cj0, i1 = cp0, ww = 0;
            if (ce1 < de || (ce1 == de && cj1 < j1)) { de = ce1; j1 = cj1; i1 = cp1; ww = 1; }
            if (ce2 < de || (ce2 == de && cj2 < j1)) { de = ce2; j1 = cj2; i1 = cp2; ww = 2; }
            if (ce3 < de || (ce3 == de && cj3 < j1)) { de = ce3; j1 = cj3; i1 = cp3; ww = 3; }
            const double delta = dec64(de);

            if (i1 == 0) {
#pragma unroll
                for (int k = 0; k < 8; k++) {
                    if ((k < 4 || g1ok) && ((usedm >> k) & 1u)) {
                        v[k] -= delta; u[rowof[k]] += delta;
                    }
                }
                if (tid == 0) {
                    u[i] += delta;
                    int jj = j1;
                    while (jj) { int jp = way[jj]; p[jj] = p[jp]; jj = jp; }
                }
                par ^= 1;
                break;
            }

            const double ui1 = u[i1];

            float4 wa = ra0, wb = rb0;
            if (ww == 1) { wa = ra1; wb = rb1; }
            if (ww == 2) { wa = ra2; wb = rb2; }
            if (ww == 3) { wa = ra3; wb = rb3; }
            rwf[0] = wa.x; rwf[1] = wa.y; rwf[2] = wa.z; rwf[3] = wa.w;
            rwf[4] = wb.x; rwf[5] = wb.y; rwf[6] = wb.z; rwf[7] = wb.w;

            bestE = ~0ULL; bestJ = Q + 2;
#pragma unroll
            for (int k = 0; k < 8; k++) {
                if (k < 4 || g1ok) {
                    if ((usedm >> k) & 1u) {
                        v[k] -= delta; u[rowof[k]] += delta;
                    } else if (colv[k] + 1 != j1) {
                        double m2  = minv[k] - delta;
                        double cur = ((double)rwf[k] - ui1) - v[k];
                        unsigned long long e2 = enc64(m2);
                        unsigned long long ec = enc64(cur);
                        if (ec < e2) { minv[k] = cur; em[k] = ec; way[colv[k] + 1] = j1; }
                        else         { minv[k] = m2;  em[k] = e2; }
                        if (em[k] < bestE) { bestE = em[k]; bestJ = colv[k] + 1; }
                    }
                }
            }
            if (tid == 0) u[i] += delta;

            {
                int c = j1 - 1, og, okk;
                if (c < 512) { og = c >> 2;        okk = c & 3; }
                else         { og = (c - 512) >> 2; okk = 4 + ((c - 512) & 3); }
                if (og == tid) { usedm |= 1u << okk; rowof[okk] = i1; }
            }
            par ^= 1;
        }
        __syncthreads();
    }

#pragma unroll
    for (int k = 0; k < 8; k++) {
        if (k < 4 || g1ok) {
            int j = colv[k] + 1;
            if (p[j] > 0) ans[p[j] - 1] = j - 1;
        }
    }
    __syncthreads();
    if (tid < TPB) {
        int a = ans[tid];
        int rank = 0;
        for (int t2 = 0; t2 < TPB; t2++) rank += (ans[t2] < a) ? 1 : 0;
        out[(size_t)C_ELEMS + (size_t)b * TPB + rank]                    = (float)a;
        out[(size_t)C_ELEMS + (size_t)BS * TPB + (size_t)b * TPB + rank] = (float)tid;
    }
}

// ---------------------------------------------------------------------------
// Cost-tile device function: computes 8 query rows of C (1600 targets each).
// ---------------------------------------------------------------------------
__device__ __noinline__ void cost_block(int tile,
                                        const float* __restrict__ logits,
                                        const float* __restrict__ boxes,
                                        const void*  __restrict__ ids,
                                        const float* __restrict__ tbox,
                                        float* __restrict__ C)
{
    __shared__ float4 c_tb[NT];
    __shared__ int    c_id[NT];
    __shared__ float  c_prob[QPB][NC];
    __shared__ float  c_box[QPB][4];

    const int tid = threadIdx.x;         // 128
    const int base_bq = tile * QPB;
    const int mode = g_idmode;

    const float4* tb4 = (const float4*)tbox;
    for (int x = tid; x < NT; x += 128) c_tb[x] = tb4[x];
    if (mode) {
        const long long* id64 = (const long long*)ids;
        for (int x = tid; x < NT; x += 128) c_id[x] = (int)id64[x];
    } else {
        const int* id32 = (const int*)ids;
        for (int x = tid; x < NT; x += 128) c_id[x] = id32[x];
    }

    const int w = tid >> 5, lane = tid & 31;
    for (int r = w; r < QPB; r += 4) {
        int bq = base_bq + r;
        const float* lr = logits + (size_t)bq * NC;
        float x0 = lr[lane];
        float x1 = lr[lane + 32];
        float x2 = (lane + 64 < NC) ? lr[lane + 64] : -1e30f;
        float m = fmaxf(x0, fmaxf(x1, x2));
        for (int o = 16; o; o >>= 1) m = fmaxf(m, __shfl_xor_sync(~0u, m, o));
        float e0 = expf(x0 - m);
        float e1 = expf(x1 - m);
        float e2 = (lane + 64 < NC) ? expf(x2 - m) : 0.0f;
        float s = e0 + e1 + e2;
        for (int o = 16; o; o >>= 1) s += __shfl_xor_sync(~0u, s, o);
        float inv = 1.0f / s;
        c_prob[r][lane]      = e0 * inv;
        c_prob[r][lane + 32] = e1 * inv;
        if (lane + 64 < NC) c_prob[r][lane + 64] = e2 * inv;
        if (lane < 4) c_box[r][lane] = boxes[(size_t)bq * 4 + lane];
    }
    __syncthreads();

    for (int r = 0; r < QPB; r++) {
        const int bq = base_bq + r;
        const float pcx = c_box[r][0], pcy = c_box[r][1];
        const float pw  = c_box[r][2], ph  = c_box[r][3];
        const float px0 = pcx - pw * 0.5f, py0 = pcy - ph * 0.5f;
        const float px1 = pcx + pw * 0.5f, py1 = pcy + ph * 0.5f;
        const float pa  = (px1 - px0) * (py1 - py0);
        float* Crow = C + (size_t)bq * NT;
        for (int j = tid; j < NT; j += 128) {
            float4 t = c_tb[j];
            float tx0 = t.x, ty0 = t.y, tx1 = t.z, ty1 = t.w;
            float tcx = (tx0 + tx1) * 0.5f, tcy = (ty0 + ty1) * 0.5f;
            float tw = tx1 - tx0, th = ty1 - ty0;
            float cbb = fabsf(pcx - tcx) + fabsf(pcy - tcy)
                      + fabsf(pw - tw) + fabsf(ph - th);
            float ta = tw * th;
            float ix0 = fmaxf(px0, tx0), iy0 = fmaxf(py0, ty0);
            float ix1 = fminf(px1, tx1), iy1 = fminf(py1, ty1);
            float iw = fmaxf(ix1 - ix0, 0.0f), ih = fmaxf(iy1 - iy0, 0.0f);
            float inter = iw * ih;
            float uni = pa + ta - inter;
            float iou = inter / uni;
            float ex0 = fminf(px0, tx0), ey0 = fminf(py0, ty0);
            float ex1 = fmaxf(px1, tx1), ey1 = fmaxf(py1, ty1);
            float cw = fmaxf(ex1 - ex0, 0.0f), ch = fmaxf(ey1 - ey0, 0.0f);
            float ca = cw * ch;
            float giou = iou - (ca - uni) / ca;
            float val = 5.0f * cbb - c_prob[r][c_id[j]] - 2.0f * giou;
            Crow[j] = val;
        }
    }
}

// ---------------------------------------------------------------------------
// Fused fat kernel: blocks 0..15 = LSA (one batch each); blocks 16.. = cost
// tiles. Single launch -> guaranteed co-residency; cost tiles drain under
// the LSA's runtime.
// ---------------------------------------------------------------------------
__global__ void __launch_bounds__(128, 1) fused_kernel(
    const float* __restrict__ logits,
    const float* __restrict__ boxes,
    const void*  __restrict__ ids,
    const float* __restrict__ tbox,
    float* __restrict__ out)
{
    if (blockIdx.x < BS) {
        lsa_block(blockIdx.x, out);
    } else {
        cost_block(blockIdx.x - BS, logits, boxes, ids, tbox, out);
    }
}

// ---------------------------------------------------------------------------
extern "C" void kernel_launch(void* const* d_in, const int* in_sizes, int n_in,
                              void* d_out, int out_size)
{
    const float* logits = (const float*)d_in[0];
    const float* boxes  = (const float*)d_in[1];
    const void*  ids    = d_in[2];
    const float* tbox   = (const float*)d_in[3];
    float* out = (float*)d_out;

    detect_ids_kernel<<<1, 128>>>((const unsigned int*)ids);
    dim3 sgrid((Q + QPB - 1) / QPB, BS);
    slice_kernel<<<sgrid, 128>>>(logits, boxes, ids, tbox);
    fused_kernel<<<BS + (BS * Q) / QPB, 128>>>(logits, boxes, ids, tbox, out);
}

// round 11
// speedup vs baseline: 1.3712x; 1.0075x over previous
#include <cuda_runtime.h>
#include <cuda_bf16.h>
#include <math.h>

#define BS 16
#define Q 900
#define NC 92
#define TPB 100
#define NT 1600
#define C_ELEMS (16*900*1600)
#define ROW_F4 (Q/4)
#define QPB 8
#define QT 113                   // ceil(900/8) query tiles per batch
#define SLICE_BLOCKS (QT*BS)     // 1808
#define COST_OFF (BS + SLICE_BLOCKS)          // 1824
#define TOTAL_BLOCKS (COST_OFF + (BS*Q)/QPB)  // 3624

__device__ float4 g_ctr4[BS * TPB * ROW_F4];
__device__ int    g_done[BS];    // per-batch slice-completion counters (self-resetting)

// ---------------------------------------------------------------------------
// Block-wide id-layout detection (int64 vs int32). Reads first 6400 bytes.
// ---------------------------------------------------------------------------
__device__ __forceinline__ int detect_mode_block(const unsigned int* __restrict__ ids)
{
    int ok = 1;
    for (int k = threadIdx.x; k < 800; k += 128) {
        unsigned lo = ids[2*k], hi = ids[2*k+1];
        if (hi != 0u || lo >= 92u) ok = 0;
    }
    return __syncthreads_and(ok);
}

// ---------------------------------------------------------------------------
// Shared-memory role overlays
// ---------------------------------------------------------------------------
struct LsaSh {
    double u[TPB + 2];
    int    p[Q + 2];
    int    way[Q + 2];
    unsigned long long s_em[2][4];
    int    s_j[2][4];
    int    s_p[2][4];
    double s_up[2][4];
    int    ans[TPB];
};
struct SliceSh {
    float4 tb[TPB];
    int    id[TPB];
    float  prob[QPB][NC];
    float  box[QPB][4];
    float  outv[TPB][QPB];
};
struct CostSh {
    float4 tb[NT];
    int    id[NT];
    float  prob[QPB][NC];
    float  box[QPB][4];
};
union AllSh { LsaSh l; SliceSh s; CostSh c; };

// ---------------------------------------------------------------------------
__device__ __forceinline__ unsigned long long enc64(double x)
{
    long long b = __double_as_longlong(x);
    return (unsigned long long)(b ^ ((b >> 63) | 0x8000000000000000LL));
}
__device__ __forceinline__ double dec64(unsigned long long e)
{
    long long b = (long long)e;
    b ^= ((~b) >> 63) | 0x8000000000000000LL;
    return __longlong_as_double(b);
}

// ---------------------------------------------------------------------------
// Slice role: one 8-query x 100-target tile, transposed into g_ctr.
// ---------------------------------------------------------------------------
__device__ void slice_block(SliceSh* sh, int b, int qtile,
                            const float* __restrict__ logits,
                            const float* __restrict__ boxes,
                            const void*  __restrict__ ids,
                            const float* __restrict__ tbox)
{
    const int tid = threadIdx.x;
    const int w = tid >> 5, lane = tid & 31;
    const int q0 = qtile * QPB;
    const int mode = detect_mode_block((const unsigned int*)ids);

    const float4* tb4 = (const float4*)tbox;
    if (tid < TPB) sh->tb[tid] = tb4[b * TPB + tid];
    if (mode) {
        const long long* id64 = (const long long*)ids;
        if (tid < TPB) sh->id[tid] = (int)id64[b * TPB + tid];
    } else {
        const int* id32 = (const int*)ids;
        if (tid < TPB) sh->id[tid] = id32[b * TPB + tid];
    }

    for (int r = w; r < QPB; r += 4) {
        int q = q0 + r;
        if (q >= Q) break;
        const float* lr = logits + ((size_t)(b * Q + q)) * NC;
        float x0 = lr[lane];
        float x1 = lr[lane + 32];
        float x2 = (lane + 64 < NC) ? lr[lane + 64] : -1e30f;
        float m = fmaxf(x0, fmaxf(x1, x2));
        for (int o = 16; o; o >>= 1) m = fmaxf(m, __shfl_xor_sync(~0u, m, o));
        float e0 = expf(x0 - m);
        float e1 = expf(x1 - m);
        float e2 = (lane + 64 < NC) ? expf(x2 - m) : 0.0f;
        float s = e0 + e1 + e2;
        for (int o = 16; o; o >>= 1) s += __shfl_xor_sync(~0u, s, o);
        float inv = 1.0f / s;
        sh->prob[r][lane]      = e0 * inv;
        sh->prob[r][lane + 32] = e1 * inv;
        if (lane + 64 < NC) sh->prob[r][lane + 64] = e2 * inv;
        if (lane < 4) sh->box[r][lane] = boxes[((size_t)(b * Q + q)) * 4 + lane];
    }
    __syncthreads();

    for (int r = 0; r < QPB; r++) {
        int q = q0 + r;
        if (q >= Q) break;
        const float pcx = sh->box[r][0], pcy = sh->box[r][1];
        const float pw  = sh->box[r][2], ph  = sh->box[r][3];
        const float px0 = pcx - pw * 0.5f, py0 = pcy - ph * 0.5f;
        const float px1 = pcx + pw * 0.5f, py1 = pcy + ph * 0.5f;
        const float pa  = (px1 - px0) * (py1 - py0);
        if (tid < TPB) {
            float4 t = sh->tb[tid];
            float tx0 = t.x, ty0 = t.y, tx1 = t.z, ty1 = t.w;
            float tcx = (tx0 + tx1) * 0.5f, tcy = (ty0 + ty1) * 0.5f;
            float tw = tx1 - tx0, th = ty1 - ty0;
            float cbb = fabsf(pcx - tcx) + fabsf(pcy - tcy)
                      + fabsf(pw - tw) + fabsf(ph - th);
            float ta = tw * th;
            float ix0 = fmaxf(px0, tx0), iy0 = fmaxf(py0, ty0);
            float ix1 = fminf(px1, tx1), iy1 = fminf(py1, ty1);
            float iw = fmaxf(ix1 - ix0, 0.0f), ih = fmaxf(iy1 - iy0, 0.0f);
            float inter = iw * ih;
            float uni = pa + ta - inter;
            float iou = inter / uni;
            float ex0 = fminf(px0, tx0), ey0 = fminf(py0, ty0);
            float ex1 = fmaxf(px1, tx1), ey1 = fmaxf(py1, ty1);
            float cw = fmaxf(ex1 - ex0, 0.0f), ch = fmaxf(ey1 - ey0, 0.0f);
            float ca = cw * ch;
            float giou = iou - (ca - uni) / ca;
            sh->outv[tid][r] = 5.0f * cbb - sh->prob[r][sh->id[tid]] - 2.0f * giou;
        }
    }
    __syncthreads();

    float* g_ctrf = (float*)g_ctr4;
    for (int idx = tid; idx < TPB * QPB; idx += 128) {
        int t = idx >> 3, r = idx & 7;
        int q = q0 + r;
        if (q < Q)
            g_ctrf[b * (TPB * Q) + t * Q + q] = sh->outv[t][r];
    }

    // publish: g_ctr writes visible before counter bump
    __syncthreads();
    __threadfence();
    if (tid == 0) atomicAdd(&g_done[b], 1);
}

// ---------------------------------------------------------------------------
// Cost role: 8 full query rows of C (1600 targets each).
// ---------------------------------------------------------------------------
__device__ void cost_block(CostSh* sh, int tile,
                           const float* __restrict__ logits,
                           const float* __restrict__ boxes,
                           const void*  __restrict__ ids,
                           const float* __restrict__ tbox,
                           float* __restrict__ C)
{
    const int tid = threadIdx.x;
    const int base_bq = tile * QPB;
    const int mode = detect_mode_block((const unsigned int*)ids);

    const float4* tb4 = (const float4*)tbox;
    for (int x = tid; x < NT; x += 128) sh->tb[x] = tb4[x];
    if (mode) {
        const long long* id64 = (const long long*)ids;
        for (int x = tid; x < NT; x += 128) sh->id[x] = (int)id64[x];
    } else {
        const int* id32 = (const int*)ids;
        for (int x = tid; x < NT; x += 128) sh->id[x] = id32[x];
    }

    const int w = tid >> 5, lane = tid & 31;
    for (int r = w; r < QPB; r += 4) {
        int bq = base_bq + r;
        const float* lr = logits + (size_t)bq * NC;
        float x0 = lr[lane];
        float x1 = lr[lane + 32];
        float x2 = (lane + 64 < NC) ? lr[lane + 64] : -1e30f;
        float m = fmaxf(x0, fmaxf(x1, x2));
        for (int o = 16; o; o >>= 1) m = fmaxf(m, __shfl_xor_sync(~0u, m, o));
        float e0 = expf(x0 - m);
        float e1 = expf(x1 - m);
        float e2 = (lane + 64 < NC) ? expf(x2 - m) : 0.0f;
        float s = e0 + e1 + e2;
        for (int o = 16; o; o >>= 1) s += __shfl_xor_sync(~0u, s, o);
        float inv = 1.0f / s;
        sh->prob[r][lane]      = e0 * inv;
        sh->prob[r][lane + 32] = e1 * inv;
        if (lane + 64 < NC) sh->prob[r][lane + 64] = e2 * inv;
        if (lane < 4) sh->box[r][lane] = boxes[(size_t)bq * 4 + lane];
    }
    __syncthreads();

    for (int r = 0; r < QPB; r++) {
        const int bq = base_bq + r;
        const float pcx = sh->box[r][0], pcy = sh->box[r][1];
        const float pw  = sh->box[r][2], ph  = sh->box[r][3];
        const float px0 = pcx - pw * 0.5f, py0 = pcy - ph * 0.5f;
        const float px1 = pcx + pw * 0.5f, py1 = pcy + ph * 0.5f;
        const float pa  = (px1 - px0) * (py1 - py0);
        float* Crow = C + (size_t)bq * NT;
        for (int j = tid; j < NT; j += 128) {
            float4 t = sh->tb[j];
            float tx0 = t.x, ty0 = t.y, tx1 = t.z, ty1 = t.w;
            float tcx = (tx0 + tx1) * 0.5f, tcy = (ty0 + ty1) * 0.5f;
            float tw = tx1 - tx0, th = ty1 - ty0;
            float cbb = fabsf(pcx - tcx) + fabsf(pcy - tcy)
                      + fabsf(pw - tw) + fabsf(ph - th);
            float ta = tw * th;
            float ix0 = fmaxf(px0, tx0), iy0 = fmaxf(py0, ty0);
            float ix1 = fminf(px1, tx1), iy1 = fminf(py1, ty1);
            float iw = fmaxf(ix1 - ix0, 0.0f), ih = fmaxf(iy1 - iy0, 0.0f);
            float inter = iw * ih;
            float uni = pa + ta - inter;
            float iou = inter / uni;
            float ex0 = fminf(px0, tx0), ey0 = fminf(py0, ty0);
            float ex1 = fmaxf(px1, tx1), ey1 = fmaxf(py1, ty1);
            float cw = fmaxf(ex1 - ex0, 0.0f), ch = fmaxf(ey1 - ey0, 0.0f);
            float ca = cw * ch;
            float giou = iou - (ca - uni) / ca;
            Crow[j] = 5.0f * cbb - sh->prob[r][sh->id[j]] - 2.0f * giou;
        }
    }
}

// ---------------------------------------------------------------------------
// LSA role (R8/R10 logic + pre-barrier u[candidate] publish).
// ---------------------------------------------------------------------------
__device__ void lsa_block(LsaSh* sh, int b, float* __restrict__ out)
{
    const int tid = threadIdx.x;
    const int w = tid >> 5, lane = tid & 31;
    const bool g1ok = (tid < 97);

    double v[8];
    int rowof[8];
    int colv[8];
#pragma unroll
    for (int k = 0; k < 8; k++) {
        v[k] = 0.0; rowof[k] = 0;
        colv[k] = (k < 4) ? (4 * tid + k) : (512 + 4 * tid + (k - 4));
    }

    for (int x = tid; x <= Q; x += 128) sh->p[x] = 0;
    if (tid <= TPB) sh->u[tid] = 0.0;

    // wait for this batch's slice tiles
    if (tid == 0) {
        while (atomicAdd(&g_done[b], 0) < QT) { }
    }
    __syncthreads();
    __threadfence();

    const float4* cb4 = g_ctr4 + b * (TPB * ROW_F4);

    float4 nxt0 = __ldg(&cb4[tid]);
    float4 nxt1 = g1ok ? __ldg(&cb4[128 + tid]) : make_float4(0.f,0.f,0.f,0.f);

    int par = 0;

    for (int i = 1; i <= TPB; i++) {
        if (tid == 0) sh->p[0] = i;
        double minv[8];
        unsigned long long em[8];
        unsigned usedm = 0;

        float rwf[8] = { nxt0.x, nxt0.y, nxt0.z, nxt0.w,
                         nxt1.x, nxt1.y, nxt1.z, nxt1.w };
        unsigned long long bestE = ~0ULL; int bestJ = Q + 2;
#pragma unroll
        for (int k = 0; k < 8; k++) {
            if (k < 4 || g1ok) {
                double cur = ((double)rwf[k] - 0.0) - v[k];
                minv[k] = cur; em[k] = enc64(cur); sh->way[colv[k] + 1] = 0;
                if (em[k] < bestE) { bestE = em[k]; bestJ = colv[k] + 1; }
            } else { minv[k] = 1e300; em[k] = ~0ULL; }
        }

        if (i < TPB) {
            nxt0 = __ldg(&cb4[i * ROW_F4 + tid]);
            if (g1ok) nxt1 = __ldg(&cb4[i * ROW_F4 + 128 + tid]);
        }

        while (true) {
            unsigned hi  = (unsigned)(bestE >> 32);
            unsigned mhi = __reduce_min_sync(0xffffffffu, hi);
            unsigned bal = __ballot_sync(0xffffffffu, hi == mhi);
            int srcJ;
            if (__popc(bal) == 1) {
                int src = __ffs(bal) - 1;
                if (lane == src) { sh->s_em[par][w] = bestE; sh->s_j[par][w] = bestJ; }
                srcJ = __shfl_sync(0xffffffffu, bestJ, src);
            } else {
                unsigned lo  = (hi == mhi) ? (unsigned)bestE : 0xffffffffu;
                unsigned mlo = __reduce_min_sync(0xffffffffu, lo);
                unsigned cjj = (hi == mhi && (unsigned)bestE == mlo)
                               ? (unsigned)bestJ : 0x7fffffffu;
                unsigned mj  = __reduce_min_sync(0xffffffffu, cjj);
                if ((unsigned)bestJ == mj) {
                    sh->s_em[par][w] = ((unsigned long long)mhi << 32) | mlo;
                    sh->s_j[par][w]  = mj;
                }
                srcJ = (int)mj;
            }
            const int wp = sh->p[srcJ];
            if (lane == 0) { sh->s_p[par][w] = wp; sh->s_up[par][w] = sh->u[wp]; }

            float4 own0, own1;
            own0 = make_float4(0.f,0.f,0.f,0.f); own1 = own0;
            if (wp) {
                const float4* cr = cb4 + (wp - 1) * ROW_F4;
                own0 = __ldg(&cr[tid]);
                if (g1ok) own1 = __ldg(&cr[128 + tid]);
            }
            __syncthreads();                                   // ONE barrier

            unsigned long long ce0 = sh->s_em[par][0], ce1 = sh->s_em[par][1],
                               ce2 = sh->s_em[par][2], ce3 = sh->s_em[par][3];
            int cj0 = sh->s_j[par][0], cj1 = sh->s_j[par][1],
                cj2 = sh->s_j[par][2], cj3 = sh->s_j[par][3];
            int cp0 = sh->s_p[par][0], cp1 = sh->s_p[par][1],
                cp2 = sh->s_p[par][2], cp3 = sh->s_p[par][3];

            float4 ra0, rb0, ra1, rb1, ra2, rb2, ra3, rb3;
            if (w == 0) { ra0 = own0; rb0 = own1; }
            else if (cp0) { const float4* cr = cb4 + (cp0 - 1) * ROW_F4;
                ra0 = __ldg(&cr[tid]); if (g1ok) rb0 = __ldg(&cr[128 + tid]); }
            if (w == 1) { ra1 = own0; rb1 = own1; }
            else if (cp1) { const float4* cr = cb4 + (cp1 - 1) * ROW_F4;
                ra1 = __ldg(&cr[tid]); if (g1ok) rb1 = __ldg(&cr[128 + tid]); }
            if (w == 2) { ra2 = own0; rb2 = own1; }
            else if (cp2) { const float4* cr = cb4 + (cp2 - 1) * ROW_F4;
                ra2 = __ldg(&cr[tid]); if (g1ok) rb2 = __ldg(&cr[128 + tid]); }
            if (w == 3) { ra3 = own0; rb3 = own1; }
            else if (cp3) { const float4* cr = cb4 + (cp3 - 1) * ROW_F4;
                ra3 = __ldg(&cr[tid]); if (g1ok) rb3 = __ldg(&cr[128 + tid]); }

            unsigned long long de = ce0; int j1 = cj0, i1 = cp0, ww = 0;
            if (ce1 < de || (ce1 == de && cj1 < j1)) { de = ce1; j1 = cj1; i1 = cp1; ww = 1; }
            if (ce2 < de || (ce2 == de && cj2 < j1)) { de = ce2; j1 = cj2; i1 = cp2; ww = 2; }
            if (ce3 < de || (ce3 == de && cj3 < j1)) { de = ce3; j1 = cj3; i1 = cp3; ww = 3; }
            const double delta = dec64(de);

            if (i1 == 0) {
#pragma unroll
                for (int k = 0; k < 8; k++) {
                    if ((k < 4 || g1ok) && ((usedm >> k) & 1u)) {
                        v[k] -= delta; sh->u[rowof[k]] += delta;
                    }
                }
                if (tid == 0) {
                    sh->u[i] += delta;
                    int jj = j1;
                    while (jj) { int jp = sh->way[jj]; sh->p[jj] = sh->p[jp]; jj = jp; }
                }
                par ^= 1;
                break;
            }

            const double ui1 = sh->s_up[par][ww];   // == u[i1], round-stable

            float4 wa = ra0, wb = rb0;
            if (ww == 1) { wa = ra1; wb = rb1; }
            if (ww == 2) { wa = ra2; wb = rb2; }
            if (ww == 3) { wa = ra3; wb = rb3; }
            rwf[0] = wa.x; rwf[1] = wa.y; rwf[2] = wa.z; rwf[3] = wa.w;
            rwf[4] = wb.x; rwf[5] = wb.y; rwf[6] = wb.z; rwf[7] = wb.w;

            bestE = ~0ULL; bestJ = Q + 2;
#pragma unroll
            for (int k = 0; k < 8; k++) {
                if (k < 4 || g1ok) {
                    if ((usedm >> k) & 1u) {
                        v[k] -= delta; sh->u[rowof[k]] += delta;
                    } else if (colv[k] + 1 != j1) {
                        double m2  = minv[k] - delta;
                        double cur = ((double)rwf[k] - ui1) - v[k];
                        unsigned long long e2 = enc64(m2);
                        unsigned long long ec = enc64(cur);
                        if (ec < e2) { minv[k] = cur; em[k] = ec; sh->way[colv[k] + 1] = j1; }
                        else         { minv[k] = m2;  em[k] = e2; }
                        if (em[k] < bestE) { bestE = em[k]; bestJ = colv[k] + 1; }
                    }
                }
            }
            if (tid == 0) sh->u[i] += delta;

            {
                int c = j1 - 1, og, okk;
                if (c < 512) { og = c >> 2;        okk = c & 3; }
                else         { og = (c - 512) >> 2; okk = 4 + ((c - 512) & 3); }
                if (og == tid) { usedm |= 1u << okk; rowof[okk] = i1; }
            }
            par ^= 1;
        }
        __syncthreads();
    }

#pragma unroll
    for (int k = 0; k < 8; k++) {
        if (k < 4 || g1ok) {
            int j = colv[k] + 1;
            if (sh->p[j] > 0) sh->ans[sh->p[j] - 1] = j - 1;
        }
    }
    __syncthreads();
    if (tid < TPB) {
        int a = sh->ans[tid];
        int rank = 0;
        for (int t2 = 0; t2 < TPB; t2++) rank += (sh->ans[t2] < a) ? 1 : 0;
        out[(size_t)C_ELEMS + (size_t)b * TPB + rank]                    = (float)a;
        out[(size_t)C_ELEMS + (size_t)BS * TPB + (size_t)b * TPB + rank] = (float)tid;
    }
    __syncthreads();
    if (tid == 0) atomicSub(&g_done[b], QT);   // restore 0 for next replay
}

// ---------------------------------------------------------------------------
// Mega kernel: blocks 0..15 LSA | 16..1823 slice | 1824..3623 cost.
// ---------------------------------------------------------------------------
__global__ void __launch_bounds__(128, 1) mega_kernel(
    const float* __restrict__ logits,
    const float* __restrict__ boxes,
    const void*  __restrict__ ids,
    const float* __restrict__ tbox,
    float* __restrict__ out)
{
    __shared__ AllSh sh;
    const int bid = blockIdx.x;
    if (bid < BS) {
        lsa_block(&sh.l, bid, out);
    } else if (bid < COST_OFF) {
        int sidx = bid - BS;
        slice_block(&sh.s, sidx & 15, sidx >> 4, logits, boxes, ids, tbox);
    } else {
        cost_block(&sh.c, bid - COST_OFF, logits, boxes, ids, tbox, out);
    }
}

// ---------------------------------------------------------------------------
extern "C" void kernel_launch(void* const* d_in, const int* in_sizes, int n_in,
                              void* d_out, int out_size)
{
    const float* logits = (const float*)d_in[0];
    const float* boxes  = (const float*)d_in[1];
    const void*  ids    = d_in[2];
    const float* tbox   = (const float*)d_in[3];
    float* out = (float*)d_out;

    mega_kernel<<<TOTAL_BLOCKS, 128>>>(logits, boxes, ids, tbox, out);
}

// round 12
// speedup vs baseline: 1.4090x; 1.0276x over previous
#include <cuda_runtime.h>
#include <cuda_bf16.h>
#include <math.h>

#define BS 16
#define Q 900
#define NC 92
#define TPB 100
#define NT 1600
#define C_ELEMS (16*900*1600)
#define ROW_F4 (Q/4)
#define QPB 8
#define QT 113                   // ceil(900/8) query tiles per batch
#define SLICE_BLOCKS (QT*BS)     // 1808
#define COST_OFF (BS + SLICE_BLOCKS)          // 1824
#define TOTAL_BLOCKS (COST_OFF + (BS*Q)/QPB)  // 3624

__device__ float4 g_ctr4[BS * TPB * ROW_F4];
__device__ int    g_done[BS];    // per-batch slice-completion counters (self-resetting)

// ---------------------------------------------------------------------------
__device__ __forceinline__ int detect_mode_block(const unsigned int* __restrict__ ids)
{
    int ok = 1;
    for (int k = threadIdx.x; k < 800; k += 128) {
        unsigned lo = ids[2*k], hi = ids[2*k+1];
        if (hi != 0u || lo >= 92u) ok = 0;
    }
    return __syncthreads_and(ok);
}

// ---------------------------------------------------------------------------
struct LsaSh {
    double u[TPB + 2];
    int    p[Q + 2];
    int    way[Q + 2];
    unsigned long long s_em[2][4];
    int    s_j[2][4];
    int    s_p[2][4];
    double s_up[2][4];
    int    ans[TPB];
};
struct SliceSh {
    float4 tb[TPB];
    int    id[TPB];
    float  prob[QPB][NC];
    float  box[QPB][4];
    float  outv[TPB][QPB];
};
struct CostSh {
    float4 tb[NT];
    int    id[NT];
    float  prob[QPB][NC];
    float  box[QPB][4];
};
union AllSh { LsaSh l; SliceSh s; CostSh c; };

// ---------------------------------------------------------------------------
__device__ __forceinline__ unsigned long long enc64(double x)
{
    long long b = __double_as_longlong(x);
    return (unsigned long long)(b ^ ((b >> 63) | 0x8000000000000000LL));
}
__device__ __forceinline__ double dec64(unsigned long long e)
{
    long long b = (long long)e;
    b ^= ((~b) >> 63) | 0x8000000000000000LL;
    return __longlong_as_double(b);
}

// ---------------------------------------------------------------------------
__device__ void slice_block(SliceSh* sh, int b, int qtile,
                            const float* __restrict__ logits,
                            const float* __restrict__ boxes,
                            const void*  __restrict__ ids,
                            const float* __restrict__ tbox)
{
    const int tid = threadIdx.x;
    const int w = tid >> 5, lane = tid & 31;
    const int q0 = qtile * QPB;
    const int mode = detect_mode_block((const unsigned int*)ids);

    const float4* tb4 = (const float4*)tbox;
    if (tid < TPB) sh->tb[tid] = tb4[b * TPB + tid];
    if (mode) {
        const long long* id64 = (const long long*)ids;
        if (tid < TPB) sh->id[tid] = (int)id64[b * TPB + tid];
    } else {
        const int* id32 = (const int*)ids;
        if (tid < TPB) sh->id[tid] = id32[b * TPB + tid];
    }

    for (int r = w; r < QPB; r += 4) {
        int q = q0 + r;
        if (q >= Q) break;
        const float* lr = logits + ((size_t)(b * Q + q)) * NC;
        float x0 = lr[lane];
        float x1 = lr[lane + 32];
        float x2 = (lane + 64 < NC) ? lr[lane + 64] : -1e30f;
        float m = fmaxf(x0, fmaxf(x1, x2));
        for (int o = 16; o; o >>= 1) m = fmaxf(m, __shfl_xor_sync(~0u, m, o));
        float e0 = expf(x0 - m);
        float e1 = expf(x1 - m);
        float e2 = (lane + 64 < NC) ? expf(x2 - m) : 0.0f;
        float s = e0 + e1 + e2;
        for (int o = 16; o; o >>= 1) s += __shfl_xor_sync(~0u, s, o);
        float inv = 1.0f / s;
        sh->prob[r][lane]      = e0 * inv;
        sh->prob[r][lane + 32] = e1 * inv;
        if (lane + 64 < NC) sh->prob[r][lane + 64] = e2 * inv;
        if (lane < 4) sh->box[r][lane] = boxes[((size_t)(b * Q + q)) * 4 + lane];
    }
    __syncthreads();

    for (int r = 0; r < QPB; r++) {
        int q = q0 + r;
        if (q >= Q) break;
        const float pcx = sh->box[r][0], pcy = sh->box[r][1];
        const float pw  = sh->box[r][2], ph  = sh->box[r][3];
        const float px0 = pcx - pw * 0.5f, py0 = pcy - ph * 0.5f;
        const float px1 = pcx + pw * 0.5f, py1 = pcy + ph * 0.5f;
        const float pa  = (px1 - px0) * (py1 - py0);
        if (tid < TPB) {
            float4 t = sh->tb[tid];
            float tx0 = t.x, ty0 = t.y, tx1 = t.z, ty1 = t.w;
            float tcx = (tx0 + tx1) * 0.5f, tcy = (ty0 + ty1) * 0.5f;
            float tw = tx1 - tx0, th = ty1 - ty0;
            float cbb = fabsf(pcx - tcx) + fabsf(pcy - tcy)
                      + fabsf(pw - tw) + fabsf(ph - th);
            float ta = tw * th;
            float ix0 = fmaxf(px0, tx0), iy0 = fmaxf(py0, ty0);
            float ix1 = fminf(px1, tx1), iy1 = fminf(py1, ty1);
            float iw = fmaxf(ix1 - ix0, 0.0f), ih = fmaxf(iy1 - iy0, 0.0f);
            float inter = iw * ih;
            float uni = pa + ta - inter;
            float iou = inter / uni;
            float ex0 = fminf(px0, tx0), ey0 = fminf(py0, ty0);
            float ex1 = fmaxf(px1, tx1), ey1 = fmaxf(py1, ty1);
            float cw = fmaxf(ex1 - ex0, 0.0f), ch = fmaxf(ey1 - ey0, 0.0f);
            float ca = cw * ch;
            float giou = iou - (ca - uni) / ca;
            sh->outv[tid][r] = 5.0f * cbb - sh->prob[r][sh->id[tid]] - 2.0f * giou;
        }
    }
    __syncthreads();

    float* g_ctrf = (float*)g_ctr4;
    for (int idx = tid; idx < TPB * QPB; idx += 128) {
        int t = idx >> 3, r = idx & 7;
        int q = q0 + r;
        if (q < Q)
            g_ctrf[b * (TPB * Q) + t * Q + q] = sh->outv[t][r];
    }

    __syncthreads();
    __threadfence();
    if (tid == 0) atomicAdd(&g_done[b], 1);
}

// ---------------------------------------------------------------------------
__device__ void cost_block(CostSh* sh, int tile,
                           const float* __restrict__ logits,
                           const float* __restrict__ boxes,
                           const void*  __restrict__ ids,
                           const float* __restrict__ tbox,
                           float* __restrict__ C)
{
    const int tid = threadIdx.x;
    const int base_bq = tile * QPB;
    const int mode = detect_mode_block((const unsigned int*)ids);

    const float4* tb4 = (const float4*)tbox;
    for (int x = tid; x < NT; x += 128) sh->tb[x] = tb4[x];
    if (mode) {
        const long long* id64 = (const long long*)ids;
        for (int x = tid; x < NT; x += 128) sh->id[x] = (int)id64[x];
    } else {
        const int* id32 = (const int*)ids;
        for (int x = tid; x < NT; x += 128) sh->id[x] = id32[x];
    }

    const int w = tid >> 5, lane = tid & 31;
    for (int r = w; r < QPB; r += 4) {
        int bq = base_bq + r;
        const float* lr = logits + (size_t)bq * NC;
        float x0 = lr[lane];
        float x1 = lr[lane + 32];
        float x2 = (lane + 64 < NC) ? lr[lane + 64] : -1e30f;
        float m = fmaxf(x0, fmaxf(x1, x2));
        for (int o = 16; o; o >>= 1) m = fmaxf(m, __shfl_xor_sync(~0u, m, o));
        float e0 = expf(x0 - m);
        float e1 = expf(x1 - m);
        float e2 = (lane + 64 < NC) ? expf(x2 - m) : 0.0f;
        float s = e0 + e1 + e2;
        for (int o = 16; o; o >>= 1) s += __shfl_xor_sync(~0u, s, o);
        float inv = 1.0f / s;
        sh->prob[r][lane]      = e0 * inv;
        sh->prob[r][lane + 32] = e1 * inv;
        if (lane + 64 < NC) sh->prob[r][lane + 64] = e2 * inv;
        if (lane < 4) sh->box[r][lane] = boxes[(size_t)bq * 4 + lane];
    }
    __syncthreads();

    for (int r = 0; r < QPB; r++) {
        const int bq = base_bq + r;
        const float pcx = sh->box[r][0], pcy = sh->box[r][1];
        const float pw  = sh->box[r][2], ph  = sh->box[r][3];
        const float px0 = pcx - pw * 0.5f, py0 = pcy - ph * 0.5f;
        const float px1 = pcx + pw * 0.5f, py1 = pcy + ph * 0.5f;
        const float pa  = (px1 - px0) * (py1 - py0);
        float* Crow = C + (size_t)bq * NT;
        for (int j = tid; j < NT; j += 128) {
            float4 t = sh->tb[j];
            float tx0 = t.x, ty0 = t.y, tx1 = t.z, ty1 = t.w;
            float tcx = (tx0 + tx1) * 0.5f, tcy = (ty0 + ty1) * 0.5f;
            float tw = tx1 - tx0, th = ty1 - ty0;
            float cbb = fabsf(pcx - tcx) + fabsf(pcy - tcy)
                      + fabsf(pw - tw) + fabsf(ph - th);
            float ta = tw * th;
            float ix0 = fmaxf(px0, tx0), iy0 = fmaxf(py0, ty0);
            float ix1 = fminf(px1, tx1), iy1 = fminf(py1, ty1);
            float iw = fmaxf(ix1 - ix0, 0.0f), ih = fmaxf(iy1 - iy0, 0.0f);
            float inter = iw * ih;
            float uni = pa + ta - inter;
            float iou = inter / uni;
            float ex0 = fminf(px0, tx0), ey0 = fminf(py0, ty0);
            float ex1 = fmaxf(px1, tx1), ey1 = fmaxf(py1, ty1);
            float cw = fmaxf(ex1 - ex0, 0.0f), ch = fmaxf(ey1 - ey0, 0.0f);
            float ca = cw * ch;
            float giou = iou - (ca - uni) / ca;
            Crow[j] = 5.0f * cbb - sh->prob[r][sh->id[j]] - 2.0f * giou;
        }
    }
}

// ---------------------------------------------------------------------------
// LSA role: two-pass update (m2 pass hides candidate-row load latency,
// cur pass after winner-select). Reference-exact fp64 sequence.
// ---------------------------------------------------------------------------
__device__ void lsa_block(LsaSh* sh, int b, float* __restrict__ out)
{
    const int tid = threadIdx.x;
    const int w = tid >> 5, lane = tid & 31;
    const bool g1ok = (tid < 97);

    double v[8];
    int rowof[8];
    int colv[8];
#pragma unroll
    for (int k = 0; k < 8; k++) {
        v[k] = 0.0; rowof[k] = 0;
        colv[k] = (k < 4) ? (4 * tid + k) : (512 + 4 * tid + (k - 4));
    }

    for (int x = tid; x <= Q; x += 128) sh->p[x] = 0;
    if (tid <= TPB) sh->u[tid] = 0.0;

    if (tid == 0) {
        while (atomicAdd(&g_done[b], 0) < QT) { }
    }
    __syncthreads();
    __threadfence();

    const float4* cb4 = g_ctr4 + b * (TPB * ROW_F4);

    float4 nxt0 = __ldg(&cb4[tid]);
    float4 nxt1 = g1ok ? __ldg(&cb4[128 + tid]) : make_float4(0.f,0.f,0.f,0.f);

    int par = 0;

    for (int i = 1; i <= TPB; i++) {
        if (tid == 0) sh->p[0] = i;
        double minv[8];
        unsigned long long em[8];
        unsigned usedm = 0;

        float rwf[8] = { nxt0.x, nxt0.y, nxt0.z, nxt0.w,
                         nxt1.x, nxt1.y, nxt1.z, nxt1.w };
        unsigned long long bestE = ~0ULL; int bestJ = Q + 2;
#pragma unroll
        for (int k = 0; k < 8; k++) {
            if (k < 4 || g1ok) {
                double cur = ((double)rwf[k] - 0.0) - v[k];
                minv[k] = cur; em[k] = enc64(cur); sh->way[colv[k] + 1] = 0;
                if (em[k] < bestE) { bestE = em[k]; bestJ = colv[k] + 1; }
            } else { minv[k] = 1e300; em[k] = ~0ULL; }
        }

        if (i < TPB) {
            nxt0 = __ldg(&cb4[i * ROW_F4 + tid]);
            if (g1ok) nxt1 = __ldg(&cb4[i * ROW_F4 + 128 + tid]);
        }

        while (true) {
            unsigned hi  = (unsigned)(bestE >> 32);
            unsigned mhi = __reduce_min_sync(0xffffffffu, hi);
            unsigned bal = __ballot_sync(0xffffffffu, hi == mhi);
            int srcJ;
            if (__popc(bal) == 1) {
                int src = __ffs(bal) - 1;
                if (lane == src) { sh->s_em[par][w] = bestE; sh->s_j[par][w] = bestJ; }
                srcJ = __shfl_sync(0xffffffffu, bestJ, src);
            } else {
                unsigned lo  = (hi == mhi) ? (unsigned)bestE : 0xffffffffu;
                unsigned mlo = __reduce_min_sync(0xffffffffu, lo);
                unsigned cjj = (hi == mhi && (unsigned)bestE == mlo)
                               ? (unsigned)bestJ : 0x7fffffffu;
                unsigned mj  = __reduce_min_sync(0xffffffffu, cjj);
                if ((unsigned)bestJ == mj) {
                    sh->s_em[par][w] = ((unsigned long long)mhi << 32) | mlo;
                    sh->s_j[par][w]  = mj;
                }
                srcJ = (int)mj;
            }
            const int wp = sh->p[srcJ];
            if (lane == 0) { sh->s_p[par][w] = wp; sh->s_up[par][w] = sh->u[wp]; }

            float4 own0, own1;
            own0 = make_float4(0.f,0.f,0.f,0.f); own1 = own0;
            if (wp) {
                const float4* cr = cb4 + (wp - 1) * ROW_F4;
                own0 = __ldg(&cr[tid]);
                if (g1ok) own1 = __ldg(&cr[128 + tid]);
            }
            __syncthreads();                                   // ONE barrier

            unsigned long long ce0 = sh->s_em[par][0], ce1 = sh->s_em[par][1],
                               ce2 = sh->s_em[par][2], ce3 = sh->s_em[par][3];
            int cj0 = sh->s_j[par][0], cj1 = sh->s_j[par][1],
                cj2 = sh->s_j[par][2], cj3 = sh->s_j[par][3];
            int cp0 = sh->s_p[par][0], cp1 = sh->s_p[par][1],
                cp2 = sh->s_p[par][2], cp3 = sh->s_p[par][3];

            // issue all candidate-row loads NOW; data not needed until pass 2
            float4 ra0, rb0, ra1, rb1, ra2, rb2, ra3, rb3;
            if (w == 0) { ra0 = own0; rb0 = own1; }
            else if (cp0) { const float4* cr = cb4 + (cp0 - 1) * ROW_F4;
                ra0 = __ldg(&cr[tid]); if (g1ok) rb0 = __ldg(&cr[128 + tid]); }
            if (w == 1) { ra1 = own0; rb1 = own1; }
            else if (cp1) { const float4* cr = cb4 + (cp1 - 1) * ROW_F4;
                ra1 = __ldg(&cr[tid]); if (g1ok) rb1 = __ldg(&cr[128 + tid]); }
            if (w == 2) { ra2 = own0; rb2 = own1; }
            else if (cp2) { const float4* cr = cb4 + (cp2 - 1) * ROW_F4;
                ra2 = __ldg(&cr[tid]); if (g1ok) rb2 = __ldg(&cr[128 + tid]); }
            if (w == 3) { ra3 = own0; rb3 = own1; }
            else if (cp3) { const float4* cr = cb4 + (cp3 - 1) * ROW_F4;
                ra3 = __ldg(&cr[tid]); if (g1ok) rb3 = __ldg(&cr[128 + tid]); }

            unsigned long long de = ce0; int j1 = cj0, i1 = cp0, ww = 0;
            if (ce1 < de || (ce1 == de && cj1 < j1)) { de = ce1; j1 = cj1; i1 = cp1; ww = 1; }
            if (ce2 < de || (ce2 == de && cj2 < j1)) { de = ce2; j1 = cj2; i1 = cp2; ww = 2; }
            if (ce3 < de || (ce3 == de && cj3 < j1)) { de = ce3; j1 = cj3; i1 = cp3; ww = 3; }
            const double delta = dec64(de);

            if (i1 == 0) {
#pragma unroll
                for (int k = 0; k < 8; k++) {
                    if ((k < 4 || g1ok) && ((usedm >> k) & 1u)) {
                        v[k] -= delta; sh->u[rowof[k]] += delta;
                    }
                }
                if (tid == 0) {
                    sh->u[i] += delta;
                    int jj = j1;
                    while (jj) { int jp = sh->way[jj]; sh->p[jj] = sh->p[jp]; jj = jp; }
                }
                par ^= 1;
                break;
            }

            const double ui1 = sh->s_up[par][ww];   // == u[i1], round-stable

            // ---- PASS 1: dual updates + m2 for all unused cols (hides the
            //      candidate-row load latency; no candidate data consumed) ----
#pragma unroll
            for (int k = 0; k < 8; k++) {
                if (k < 4 || g1ok) {
                    if ((usedm >> k) & 1u) {
                        v[k] -= delta; sh->u[rowof[k]] += delta;
                    } else if (colv[k] + 1 != j1) {
                        minv[k] -= delta;            // m2 (reference order)
                        em[k] = enc64(minv[k]);
                    }
                }
            }
            if (tid == 0) sh->u[i] += delta;

            // winner row registers (loads have had the full pass-1 window)
            float4 wa = ra0, wb = rb0;
            if (ww == 1) { wa = ra1; wb = rb1; }
            if (ww == 2) { wa = ra2; wb = rb2; }
            if (ww == 3) { wa = ra3; wb = rb3; }
            rwf[0] = wa.x; rwf[1] = wa.y; rwf[2] = wa.z; rwf[3] = wa.w;
            rwf[4] = wb.x; rwf[5] = wb.y; rwf[6] = wb.z; rwf[7] = wb.w;

            // ---- PASS 2: winner-row cur merge vs m2 + best tracking ----
            bestE = ~0ULL; bestJ = Q + 2;
#pragma unroll
            for (int k = 0; k < 8; k++) {
                if ((k < 4 || g1ok) && !((usedm >> k) & 1u) && (colv[k] + 1 != j1)) {
                    double cur = ((double)rwf[k] - ui1) - v[k];
                    unsigned long long ec = enc64(cur);
                    if (ec < em[k]) { minv[k] = cur; em[k] = ec; sh->way[colv[k] + 1] = j1; }
                    if (em[k] < bestE) { bestE = em[k]; bestJ = colv[k] + 1; }
                }
            }

            {
                int c = j1 - 1, og, okk;
                if (c < 512) { og = c >> 2;        okk = c & 3; }
                else         { og = (c - 512) >> 2; okk = 4 + ((c - 512) & 3); }
                if (og == tid) { usedm |= 1u << okk; rowof[okk] = i1; }
            }
            par ^= 1;
        }
        __syncthreads();
    }

#pragma unroll
    for (int k = 0; k < 8; k++) {
        if (k < 4 || g1ok) {
            int j = colv[k] + 1;
            if (sh->p[j] > 0) sh->ans[sh->p[j] - 1] = j - 1;
        }
    }
    __syncthreads();
    if (tid < TPB) {
        int a = sh->ans[tid];
        int rank = 0;
        for (int t2 = 0; t2 < TPB; t2++) rank += (sh->ans[t2] < a) ? 1 : 0;
        out[(size_t)C_ELEMS + (size_t)b * TPB + rank]                    = (float)a;
        out[(size_t)C_ELEMS + (size_t)BS * TPB + (size_t)b * TPB + rank] = (float)tid;
    }
    __syncthreads();
    if (tid == 0) atomicSub(&g_done[b], QT);   // restore 0 for next replay
}

// ---------------------------------------------------------------------------
__global__ void __launch_bounds__(128, 1) mega_kernel(
    const float* __restrict__ logits,
    const float* __restrict__ boxes,
    const void*  __restrict__ ids,
    const float* __restrict__ tbox,
    float* __restrict__ out)
{
    __shared__ AllSh sh;
    const int bid = blockIdx.x;
    if (bid < BS) {
        lsa_block(&sh.l, bid, out);
    } else if (bid < COST_OFF) {
        int sidx = bid - BS;
        slice_block(&sh.s, sidx & 15, sidx >> 4, logits, boxes, ids, tbox);
    } else {
        cost_block(&sh.c, bid - COST_OFF, logits, boxes, ids, tbox, out);
    }
}

// ---------------------------------------------------------------------------
extern "C" void kernel_launch(void* const* d_in, const int* in_sizes, int n_in,
                              void* d_out, int out_size)
{
    const float* logits = (const float*)d_in[0];
    const float* boxes  = (const float*)d_in[1];
    const void*  ids    = d_in[2];
    const float* tbox   = (const float*)d_in[3];
    float* out = (float*)d_out;

    mega_kernel<<<TOTAL_BLOCKS, 128>>>(logits, boxes, ids, tbox, out);
}

// round 13
// speedup vs baseline: 1.4096x; 1.0005x over previous
#include <cuda_runtime.h>
#include <cuda_bf16.h>
#include <math.h>

#define BS 16
#define Q 900
#define NC 92
#define TPB 100
#define NT 1600
#define C_ELEMS (16*900*1600)
#define ROW_F4 (Q/4)
#define QPB 8
#define QT 113                   // ceil(900/8) query tiles per batch
#define SLICE_BLOCKS (QT*BS)     // 1808
#define COST_OFF (BS + SLICE_BLOCKS)          // 1824
#define TOTAL_BLOCKS (COST_OFF + (BS*Q)/QPB)  // 3624

__device__ float4 g_ctr4[BS * TPB * ROW_F4];
__device__ int    g_done[BS];    // per-batch slice-completion counters (self-resetting)

// ---------------------------------------------------------------------------
__device__ __forceinline__ int detect_mode_block(const unsigned int* __restrict__ ids)
{
    int ok = 1;
    for (int k = threadIdx.x; k < 800; k += 128) {
        unsigned lo = ids[2*k], hi = ids[2*k+1];
        if (hi != 0u || lo >= 92u) ok = 0;
    }
    return __syncthreads_and(ok);
}

// ---------------------------------------------------------------------------
struct LsaSh {
    double u[TPB + 2];
    int    p[Q + 2];
    int    way[Q + 2];
    unsigned long long s_em[2][4];
    int    s_j[2][4];
    int    s_p[2][4];
    int    ans[TPB];
};
struct SliceSh {
    float4 tb[TPB];
    int    id[TPB];
    float  prob[QPB][NC];
    float  box[QPB][4];
    float  outv[TPB][QPB];
};
struct CostSh {
    float4 tb[NT];
    int    id[NT];
    float  prob[QPB][NC];
    float  box[QPB][4];
};
union AllSh { LsaSh l; SliceSh s; CostSh c; };

// ---------------------------------------------------------------------------
__device__ __forceinline__ unsigned long long enc64(double x)
{
    long long b = __double_as_longlong(x);
    return (unsigned long long)(b ^ ((b >> 63) | 0x8000000000000000LL));
}
__device__ __forceinline__ double dec64(unsigned long long e)
{
    long long b = (long long)e;
    b ^= ((~b) >> 63) | 0x8000000000000000LL;
    return __longlong_as_double(b);
}

// ---------------------------------------------------------------------------
__device__ void slice_block(SliceSh* sh, int b, int qtile,
                            const float* __restrict__ logits,
                            const float* __restrict__ boxes,
                            const void*  __restrict__ ids,
                            const float* __restrict__ tbox)
{
    const int tid = threadIdx.x;
    const int w = tid >> 5, lane = tid & 31;
    const int q0 = qtile * QPB;
    const int mode = detect_mode_block((const unsigned int*)ids);

    const float4* tb4 = (const float4*)tbox;
    if (tid < TPB) sh->tb[tid] = tb4[b * TPB + tid];
    if (mode) {
        const long long* id64 = (const long long*)ids;
        if (tid < TPB) sh->id[tid] = (int)id64[b * TPB + tid];
    } else {
        const int* id32 = (const int*)ids;
        if (tid < TPB) sh->id[tid] = id32[b * TPB + tid];
    }

    for (int r = w; r < QPB; r += 4) {
        int q = q0 + r;
        if (q >= Q) break;
        const float* lr = logits + ((size_t)(b * Q + q)) * NC;
        float x0 = lr[lane];
        float x1 = lr[lane + 32];
        float x2 = (lane + 64 < NC) ? lr[lane + 64] : -1e30f;
        float m = fmaxf(x0, fmaxf(x1, x2));
        for (int o = 16; o; o >>= 1) m = fmaxf(m, __shfl_xor_sync(~0u, m, o));
        float e0 = expf(x0 - m);
        float e1 = expf(x1 - m);
        float e2 = (lane + 64 < NC) ? expf(x2 - m) : 0.0f;
        float s = e0 + e1 + e2;
        for (int o = 16; o; o >>= 1) s += __shfl_xor_sync(~0u, s, o);
        float inv = 1.0f / s;
        sh->prob[r][lane]      = e0 * inv;
        sh->prob[r][lane + 32] = e1 * inv;
        if (lane + 64 < NC) sh->prob[r][lane + 64] = e2 * inv;
        if (lane < 4) sh->box[r][lane] = boxes[((size_t)(b * Q + q)) * 4 + lane];
    }
    __syncthreads();

    for (int r = 0; r < QPB; r++) {
        int q = q0 + r;
        if (q >= Q) break;
        const float pcx = sh->box[r][0], pcy = sh->box[r][1];
        const float pw  = sh->box[r][2], ph  = sh->box[r][3];
        const float px0 = pcx - pw * 0.5f, py0 = pcy - ph * 0.5f;
        const float px1 = pcx + pw * 0.5f, py1 = pcy + ph * 0.5f;
        const float pa  = (px1 - px0) * (py1 - py0);
        if (tid < TPB) {
            float4 t = sh->tb[tid];
            float tx0 = t.x, ty0 = t.y, tx1 = t.z, ty1 = t.w;
            float tcx = (tx0 + tx1) * 0.5f, tcy = (ty0 + ty1) * 0.5f;
            float tw = tx1 - tx0, th = ty1 - ty0;
            float cbb = fabsf(pcx - tcx) + fabsf(pcy - tcy)
                      + fabsf(pw - tw) + fabsf(ph - th);
            float ta = tw * th;
            float ix0 = fmaxf(px0, tx0), iy0 = fmaxf(py0, ty0);
            float ix1 = fminf(px1, tx1), iy1 = fminf(py1, ty1);
            float iw = fmaxf(ix1 - ix0, 0.0f), ih = fmaxf(iy1 - iy0, 0.0f);
            float inter = iw * ih;
            float uni = pa + ta - inter;
            float iou = inter / uni;
            float ex0 = fminf(px0, tx0), ey0 = fminf(py0, ty0);
            float ex1 = fmaxf(px1, tx1), ey1 = fmaxf(py1, ty1);
            float cw = fmaxf(ex1 - ex0, 0.0f), ch = fmaxf(ey1 - ey0, 0.0f);
            float ca = cw * ch;
            float giou = iou - (ca - uni) / ca;
            sh->outv[tid][r] = 5.0f * cbb - sh->prob[r][sh->id[tid]] - 2.0f * giou;
        }
    }
    __syncthreads();

    float* g_ctrf = (float*)g_ctr4;
    for (int idx = tid; idx < TPB * QPB; idx += 128) {
        int t = idx >> 3, r = idx & 7;
        int q = q0 + r;
        if (q < Q)
            g_ctrf[b * (TPB * Q) + t * Q + q] = sh->outv[t][r];
    }

    __syncthreads();
    __threadfence();
    if (tid == 0) atomicAdd(&g_done[b], 1);
}

// ---------------------------------------------------------------------------
__device__ void cost_block(CostSh* sh, int tile,
                           const float* __restrict__ logits,
                           const float* __restrict__ boxes,
                           const void*  __restrict__ ids,
                           const float* __restrict__ tbox,
                           float* __restrict__ C)
{
    const int tid = threadIdx.x;
    const int base_bq = tile * QPB;
    const int mode = detect_mode_block((const unsigned int*)ids);

    const float4* tb4 = (const float4*)tbox;
    for (int x = tid; x < NT; x += 128) sh->tb[x] = tb4[x];
    if (mode) {
        const long long* id64 = (const long long*)ids;
        for (int x = tid; x < NT; x += 128) sh->id[x] = (int)id64[x];
    } else {
        const int* id32 = (const int*)ids;
        for (int x = tid; x < NT; x += 128) sh->id[x] = id32[x];
    }

    const int w = tid >> 5, lane = tid & 31;
    for (int r = w; r < QPB; r += 4) {
        int bq = base_bq + r;
        const float* lr = logits + (size_t)bq * NC;
        float x0 = lr[lane];
        float x1 = lr[lane + 32];
        float x2 = (lane + 64 < NC) ? lr[lane + 64] : -1e30f;
        float m = fmaxf(x0, fmaxf(x1, x2));
        for (int o = 16; o; o >>= 1) m = fmaxf(m, __shfl_xor_sync(~0u, m, o));
        float e0 = expf(x0 - m);
        float e1 = expf(x1 - m);
        float e2 = (lane + 64 < NC) ? expf(x2 - m) : 0.0f;
        float s = e0 + e1 + e2;
        for (int o = 16; o; o >>= 1) s += __shfl_xor_sync(~0u, s, o);
        float inv = 1.0f / s;
        sh->prob[r][lane]      = e0 * inv;
        sh->prob[r][lane + 32] = e1 * inv;
        if (lane + 64 < NC) sh->prob[r][lane + 64] = e2 * inv;
        if (lane < 4) sh->box[r][lane] = boxes[(size_t)bq * 4 + lane];
    }
    __syncthreads();

    for (int r = 0; r < QPB; r++) {
        const int bq = base_bq + r;
        const float pcx = sh->box[r][0], pcy = sh->box[r][1];
        const float pw  = sh->box[r][2], ph  = sh->box[r][3];
        const float px0 = pcx - pw * 0.5f, py0 = pcy - ph * 0.5f;
        const float px1 = pcx + pw * 0.5f, py1 = pcy + ph * 0.5f;
        const float pa  = (px1 - px0) * (py1 - py0);
        float* Crow = C + (size_t)bq * NT;
        for (int j = tid; j < NT; j += 128) {
            float4 t = sh->tb[j];
            float tx0 = t.x, ty0 = t.y, tx1 = t.z, ty1 = t.w;
            float tcx = (tx0 + tx1) * 0.5f, tcy = (ty0 + ty1) * 0.5f;
            float tw = tx1 - tx0, th = ty1 - ty0;
            float cbb = fabsf(pcx - tcx) + fabsf(pcy - tcy)
                      + fabsf(pw - tw) + fabsf(ph - th);
            float ta = tw * th;
            float ix0 = fmaxf(px0, tx0), iy0 = fmaxf(py0, ty0);
            float ix1 = fminf(px1, tx1), iy1 = fminf(py1, ty1);
            float iw = fmaxf(ix1 - ix0, 0.0f), ih = fmaxf(iy1 - iy0, 0.0f);
            float inter = iw * ih;
            float uni = pa + ta - inter;
            float iou = inter / uni;
            float ex0 = fminf(px0, tx0), ey0 = fminf(py0, ty0);
            float ex1 = fmaxf(px1, tx1), ey1 = fmaxf(py1, ty1);
            float cw = fmaxf(ex1 - ex0, 0.0f), ch = fmaxf(ey1 - ey0, 0.0f);
            float ca = cw * ch;
            float giou = iou - (ca - uni) / ca;
            Crow[j] = 5.0f * cbb - sh->prob[r][sh->id[j]] - 2.0f * giou;
        }
    }
}

// ---------------------------------------------------------------------------
// LSA role: two-pass update; u[i1] read post-barrier (hidden under pass1);
// t1 = (c - ui1) hoisted before pass1; tree reduces. Reference-exact fp64.
// ---------------------------------------------------------------------------
__device__ void lsa_block(LsaSh* sh, int b, float* __restrict__ out)
{
    const int tid = threadIdx.x;
    const int w = tid >> 5, lane = tid & 31;
    const bool g1ok = (tid < 97);

    double v[8];
    int rowof[8];
    int colv[8];
#pragma unroll
    for (int k = 0; k < 8; k++) {
        v[k] = 0.0; rowof[k] = 0;
        colv[k] = (k < 4) ? (4 * tid + k) : (512 + 4 * tid + (k - 4));
    }

    for (int x = tid; x <= Q; x += 128) sh->p[x] = 0;
    if (tid <= TPB) sh->u[tid] = 0.0;

    if (tid == 0) {
        while (atomicAdd(&g_done[b], 0) < QT) { }
    }
    __syncthreads();
    __threadfence();

    const float4* cb4 = g_ctr4 + b * (TPB * ROW_F4);

    float4 nxt0 = __ldg(&cb4[tid]);
    float4 nxt1 = g1ok ? __ldg(&cb4[128 + tid]) : make_float4(0.f,0.f,0.f,0.f);

    int par = 0;

    for (int i = 1; i <= TPB; i++) {
        if (tid == 0) sh->p[0] = i;
        double minv[8];
        unsigned long long em[8];
        unsigned usedm = 0;

        float rwf[8] = { nxt0.x, nxt0.y, nxt0.z, nxt0.w,
                         nxt1.x, nxt1.y, nxt1.z, nxt1.w };
        unsigned long long bestE = ~0ULL; int bestJ = Q + 2;
#pragma unroll
        for (int k = 0; k < 8; k++) {
            if (k < 4 || g1ok) {
                double cur = ((double)rwf[k] - 0.0) - v[k];
                minv[k] = cur; em[k] = enc64(cur); sh->way[colv[k] + 1] = 0;
                if (em[k] < bestE) { bestE = em[k]; bestJ = colv[k] + 1; }
            } else { minv[k] = 1e300; em[k] = ~0ULL; }
        }

        if (i < TPB) {
            nxt0 = __ldg(&cb4[i * ROW_F4 + tid]);
            if (g1ok) nxt1 = __ldg(&cb4[i * ROW_F4 + 128 + tid]);
        }

        while (true) {
            unsigned hi  = (unsigned)(bestE >> 32);
            unsigned mhi = __reduce_min_sync(0xffffffffu, hi);
            unsigned bal = __ballot_sync(0xffffffffu, hi == mhi);
            int srcJ;
            if (__popc(bal) == 1) {
                int src = __ffs(bal) - 1;
                if (lane == src) { sh->s_em[par][w] = bestE; sh->s_j[par][w] = bestJ; }
                srcJ = __shfl_sync(0xffffffffu, bestJ, src);
            } else {
                unsigned lo  = (hi == mhi) ? (unsigned)bestE : 0xffffffffu;
                unsigned mlo = __reduce_min_sync(0xffffffffu, lo);
                unsigned cjj = (hi == mhi && (unsigned)bestE == mlo)
                               ? (unsigned)bestJ : 0x7fffffffu;
                unsigned mj  = __reduce_min_sync(0xffffffffu, cjj);
                if ((unsigned)bestJ == mj) {
                    sh->s_em[par][w] = ((unsigned long long)mhi << 32) | mlo;
                    sh->s_j[par][w]  = mj;
                }
                srcJ = (int)mj;
            }
            const int wp = sh->p[srcJ];
            if (lane == 0) sh->s_p[par][w] = wp;

            float4 own0, own1;
            own0 = make_float4(0.f,0.f,0.f,0.f); own1 = own0;
            if (wp) {
                const float4* cr = cb4 + (wp - 1) * ROW_F4;
                own0 = __ldg(&cr[tid]);
                if (g1ok) own1 = __ldg(&cr[128 + tid]);
            }
            __syncthreads();                                   // ONE barrier

            unsigned long long ce0 = sh->s_em[par][0], ce1 = sh->s_em[par][1],
                               ce2 = sh->s_em[par][2], ce3 = sh->s_em[par][3];
            int cj0 = sh->s_j[par][0], cj1 = sh->s_j[par][1],
                cj2 = sh->s_j[par][2], cj3 = sh->s_j[par][3];
            int cp0 = sh->s_p[par][0], cp1 = sh->s_p[par][1],
                cp2 = sh->s_p[par][2], cp3 = sh->s_p[par][3];

            // issue all candidate-row loads NOW; data not needed until pass 2
            float4 ra0, rb0, ra1, rb1, ra2, rb2, ra3, rb3;
            if (w == 0) { ra0 = own0; rb0 = own1; }
            else if (cp0) { const float4* cr = cb4 + (cp0 - 1) * ROW_F4;
                ra0 = __ldg(&cr[tid]); if (g1ok) rb0 = __ldg(&cr[128 + tid]); }
            if (w == 1) { ra1 = own0; rb1 = own1; }
            else if (cp1) { const float4* cr = cb4 + (cp1 - 1) * ROW_F4;
                ra1 = __ldg(&cr[tid]); if (g1ok) rb1 = __ldg(&cr[128 + tid]); }
            if (w == 2) { ra2 = own0; rb2 = own1; }
            else if (cp2) { const float4* cr = cb4 + (cp2 - 1) * ROW_F4;
                ra2 = __ldg(&cr[tid]); if (g1ok) rb2 = __ldg(&cr[128 + tid]); }
            if (w == 3) { ra3 = own0; rb3 = own1; }
            else if (cp3) { const float4* cr = cb4 + (cp3 - 1) * ROW_F4;
                ra3 = __ldg(&cr[tid]); if (g1ok) rb3 = __ldg(&cr[128 + tid]); }

            // tree 4-way reduce (ties -> smaller j); track winner warp
            unsigned long long eA = ce0; int jA = cj0, pA = cp0, wA = 0;
            if (ce1 < eA || (ce1 == eA && cj1 < jA)) { eA = ce1; jA = cj1; pA = cp1; wA = 1; }
            unsigned long long eB = ce2; int jB = cj2, pB = cp2, wB = 2;
            if (ce3 < eB || (ce3 == eB && cj3 < jB)) { eB = ce3; jB = cj3; pB = cp3; wB = 3; }
            unsigned long long de = eA; int j1 = jA, i1 = pA, ww = wA;
            if (eB < de || (eB == de && jB < j1)) { de = eB; j1 = jB; i1 = pB; ww = wB; }
            const double delta = dec64(de);

            if (i1 == 0) {
#pragma unroll
                for (int k = 0; k < 8; k++) {
                    if ((k < 4 || g1ok) && ((usedm >> k) & 1u)) {
                        v[k] -= delta; sh->u[rowof[k]] += delta;
                    }
                }
                if (tid == 0) {
                    sh->u[i] += delta;
                    int jj = j1;
                    while (jj) { int jp = sh->way[jj]; sh->p[jj] = sh->p[jp]; jj = jp; }
                }
                par ^= 1;
                break;
            }

            // u[i1] read here: LDS latency hides under pass1 fp64.
            // Safe: row i1 receives no u update this iteration, and i1 != i.
            const double ui1 = sh->u[i1];

            // winner row registers
            float4 wa = ra0, wb = rb0;
            if (ww == 1) { wa = ra1; wb = rb1; }
            if (ww == 2) { wa = ra2; wb = rb2; }
            if (ww == 3) { wa = ra3; wb = rb3; }
            rwf[0] = wa.x; rwf[1] = wa.y; rwf[2] = wa.z; rwf[3] = wa.w;
            rwf[4] = wb.x; rwf[5] = wb.y; rwf[6] = wb.z; rwf[7] = wb.w;

            // t1 = (c - u[i1]) : independent of delta/v, runs parallel to pass1
            double t1[8];
#pragma unroll
            for (int k = 0; k < 8; k++) t1[k] = (double)rwf[k] - ui1;

            // ---- PASS 1: dual updates + m2 (reference order) ----
#pragma unroll
            for (int k = 0; k < 8; k++) {
                if (k < 4 || g1ok) {
                    if ((usedm >> k) & 1u) {
                        v[k] -= delta; sh->u[rowof[k]] += delta;
                    } else if (colv[k] + 1 != j1) {
                        minv[k] -= delta;
                        em[k] = enc64(minv[k]);
                    }
                }
            }
            if (tid == 0) sh->u[i] += delta;

            // ---- PASS 2: cur = t1 - v, merge vs m2, tree best-tracking ----
            unsigned long long be[8]; int bj[8];
#pragma unroll
            for (int k = 0; k < 8; k++) {
                bool act = (k < 4 || g1ok) && !((usedm >> k) & 1u)
                           && (colv[k] + 1 != j1);
                bj[k] = colv[k] + 1;
                if (act) {
                    double cur = t1[k] - v[k];
                    unsigned long long ec = enc64(cur);
                    if (ec < em[k]) { minv[k] = cur; em[k] = ec; sh->way[bj[k]] = j1; }
                    be[k] = em[k];
                } else {
                    be[k] = ~0ULL;
                }
            }
            // depth-3 tree (ties -> smaller j; per-thread colv ascending in k)
#pragma unroll
            for (int s = 1; s < 8; s <<= 1) {
#pragma unroll
                for (int k = 0; k < 8; k += 2 * s) {
                    if (be[k + s] < be[k] ||
                        (be[k + s] == be[k] && bj[k + s] < bj[k])) {
                        be[k] = be[k + s]; bj[k] = bj[k + s];
                    }
                }
            }
            bestE = be[0]; bestJ = bj[0];

            {
                int c = j1 - 1, og, okk;
                if (c < 512) { og = c >> 2;        okk = c & 3; }
                else         { og = (c - 512) >> 2; okk = 4 + ((c - 512) & 3); }
                if (og == tid) { usedm |= 1u << okk; rowof[okk] = i1; }
            }
            par ^= 1;
        }
        __syncthreads();
    }

#pragma unroll
    for (int k = 0; k < 8; k++) {
        if (k < 4 || g1ok) {
            int j = colv[k] + 1;
            if (sh->p[j] > 0) sh->ans[sh->p[j] - 1] = j - 1;
        }
    }
    __syncthreads();
    if (tid < TPB) {
        int a = sh->ans[tid];
        int rank = 0;
        for (int t2 = 0; t2 < TPB; t2++) rank += (sh->ans[t2] < a) ? 1 : 0;
        out[(size_t)C_ELEMS + (size_t)b * TPB + rank]                    = (float)a;
        out[(size_t)C_ELEMS + (size_t)BS * TPB + (size_t)b * TPB + rank] = (float)tid;
    }
    __syncthreads();
    if (tid == 0) atomicSub(&g_done[b], QT);   // restore 0 for next replay
}

// ---------------------------------------------------------------------------
__global__ void __launch_bounds__(128, 1) mega_kernel(
    const float* __restrict__ logits,
    const float* __restrict__ boxes,
    const void*  __restrict__ ids,
    const float* __restrict__ tbox,
    float* __restrict__ out)
{
    __shared__ AllSh sh;
    const int bid = blockIdx.x;
    if (bid < BS) {
        lsa_block(&sh.l, bid, out);
    } else if (bid < COST_OFF) {
        int sidx = bid - BS;
        slice_block(&sh.s, sidx & 15, sidx >> 4, logits, boxes, ids, tbox);
    } else {
        cost_block(&sh.c, bid - COST_OFF, logits, boxes, ids, tbox, out);
    }
}

// ---------------------------------------------------------------------------
extern "C" void kernel_launch(void* const* d_in, const int* in_sizes, int n_in,
                              void* d_out, int out_size)
{
    const float* logits = (const float*)d_in[0];
    const float* boxes  = (const float*)d_in[1];
    const void*  ids    = d_in[2];
    const float* tbox   = (const float*)d_in[3];
    float* out = (float*)d_out;

    mega_kernel<<<TOTAL_BLOCKS, 128>>>(logits, boxes, ids, tbox, out);
}

// round 14
// speedup vs baseline: 1.5338x; 1.0881x over previous
#include <cuda_runtime.h>
#include <cuda_bf16.h>
#include <math.h>

#define BS 16
#define Q 900
#define NC 92
#define TPB 100
#define NT 1600
#define C_ELEMS (16*900*1600)
#define ROW_F4 (Q/4)
#define QPB 8
#define QT 113                   // ceil(900/8) query tiles per batch
#define SLICE_BLOCKS (QT*BS)     // 1808
#define COST_OFF (BS + SLICE_BLOCKS)          // 1824
#define TOTAL_BLOCKS (COST_OFF + (BS*Q)/QPB)  // 3624

__device__ float4 g_ctr4[BS * TPB * ROW_F4];
__device__ int    g_done[BS];    // per-batch slice-completion counters (self-resetting)

// ---------------------------------------------------------------------------
__device__ __forceinline__ int detect_mode_block(const unsigned int* __restrict__ ids)
{
    int ok = 1;
    for (int k = threadIdx.x; k < 800; k += 128) {
        unsigned lo = ids[2*k], hi = ids[2*k+1];
        if (hi != 0u || lo >= 92u) ok = 0;
    }
    return __syncthreads_and(ok);
}

// ---------------------------------------------------------------------------
struct LsaSh {
    double u[TPB + 2];
    int    p[Q + 2];
    int    way[Q + 2];
    unsigned long long s_em[2][4];
    int    s_j[2][4];
    int    s_p[2][4];
    int    ans[TPB];
};
struct SliceSh {
    float4 tb[TPB];
    int    id[TPB];
    float  prob[QPB][NC];
    float  box[QPB][4];
    float  outv[TPB][QPB];
};
struct CostSh {
    float4 tb[NT];
    int    id[NT];
    float  prob[QPB][NC];
    float  box[QPB][4];
};
union AllSh { LsaSh l; SliceSh s; CostSh c; };

// ---------------------------------------------------------------------------
__device__ __forceinline__ unsigned long long enc64(double x)
{
    long long b = __double_as_longlong(x);
    return (unsigned long long)(b ^ ((b >> 63) | 0x8000000000000000LL));
}
__device__ __forceinline__ double dec64(unsigned long long e)
{
    long long b = (long long)e;
    b ^= ((~b) >> 63) | 0x8000000000000000LL;
    return __longlong_as_double(b);
}

// ---------------------------------------------------------------------------
__device__ void slice_block(SliceSh* sh, int b, int qtile,
                            const float* __restrict__ logits,
                            const float* __restrict__ boxes,
                            const void*  __restrict__ ids,
                            const float* __restrict__ tbox)
{
    const int tid = threadIdx.x;
    const int w = tid >> 5, lane = tid & 31;
    const int q0 = qtile * QPB;
    const int mode = detect_mode_block((const unsigned int*)ids);

    const float4* tb4 = (const float4*)tbox;
    if (tid < TPB) sh->tb[tid] = tb4[b * TPB + tid];
    if (mode) {
        const long long* id64 = (const long long*)ids;
        if (tid < TPB) sh->id[tid] = (int)id64[b * TPB + tid];
    } else {
        const int* id32 = (const int*)ids;
        if (tid < TPB) sh->id[tid] = id32[b * TPB + tid];
    }

    for (int r = w; r < QPB; r += 4) {
        int q = q0 + r;
        if (q >= Q) break;
        const float* lr = logits + ((size_t)(b * Q + q)) * NC;
        float x0 = lr[lane];
        float x1 = lr[lane + 32];
        float x2 = (lane + 64 < NC) ? lr[lane + 64] : -1e30f;
        float m = fmaxf(x0, fmaxf(x1, x2));
        for (int o = 16; o; o >>= 1) m = fmaxf(m, __shfl_xor_sync(~0u, m, o));
        float e0 = expf(x0 - m);
        float e1 = expf(x1 - m);
        float e2 = (lane + 64 < NC) ? expf(x2 - m) : 0.0f;
        float s = e0 + e1 + e2;
        for (int o = 16; o; o >>= 1) s += __shfl_xor_sync(~0u, s, o);
        float inv = 1.0f / s;
        sh->prob[r][lane]      = e0 * inv;
        sh->prob[r][lane + 32] = e1 * inv;
        if (lane + 64 < NC) sh->prob[r][lane + 64] = e2 * inv;
        if (lane < 4) sh->box[r][lane] = boxes[((size_t)(b * Q + q)) * 4 + lane];
    }
    __syncthreads();

    for (int r = 0; r < QPB; r++) {
        int q = q0 + r;
        if (q >= Q) break;
        const float pcx = sh->box[r][0], pcy = sh->box[r][1];
        const float pw  = sh->box[r][2], ph  = sh->box[r][3];
        const float px0 = pcx - pw * 0.5f, py0 = pcy - ph * 0.5f;
        const float px1 = pcx + pw * 0.5f, py1 = pcy + ph * 0.5f;
        const float pa  = (px1 - px0) * (py1 - py0);
        if (tid < TPB) {
            float4 t = sh->tb[tid];
            float tx0 = t.x, ty0 = t.y, tx1 = t.z, ty1 = t.w;
            float tcx = (tx0 + tx1) * 0.5f, tcy = (ty0 + ty1) * 0.5f;
            float tw = tx1 - tx0, th = ty1 - ty0;
            float cbb = fabsf(pcx - tcx) + fabsf(pcy - tcy)
                      + fabsf(pw - tw) + fabsf(ph - th);
            float ta = tw * th;
            float ix0 = fmaxf(px0, tx0), iy0 = fmaxf(py0, ty0);
            float ix1 = fminf(px1, tx1), iy1 = fminf(py1, ty1);
            float iw = fmaxf(ix1 - ix0, 0.0f), ih = fmaxf(iy1 - iy0, 0.0f);
            float inter = iw * ih;
            float uni = pa + ta - inter;
            float iou = inter / uni;
            float ex0 = fminf(px0, tx0), ey0 = fminf(py0, ty0);
            float ex1 = fmaxf(px1, tx1), ey1 = fmaxf(py1, ty1);
            float cw = fmaxf(ex1 - ex0, 0.0f), ch = fmaxf(ey1 - ey0, 0.0f);
            float ca = cw * ch;
            float giou = iou - (ca - uni) / ca;
            sh->outv[tid][r] = 5.0f * cbb - sh->prob[r][sh->id[tid]] - 2.0f * giou;
        }
    }
    __syncthreads();

    float* g_ctrf = (float*)g_ctr4;
    for (int idx = tid; idx < TPB * QPB; idx += 128) {
        int t = idx >> 3, r = idx & 7;
        int q = q0 + r;
        if (q < Q)
            g_ctrf[b * (TPB * Q) + t * Q + q] = sh->outv[t][r];
    }

    __syncthreads();
    __threadfence();
    if (tid == 0) atomicAdd(&g_done[b], 1);
}

// ---------------------------------------------------------------------------
__device__ void cost_block(CostSh* sh, int tile,
                           const float* __restrict__ logits,
                           const float* __restrict__ boxes,
                           const void*  __restrict__ ids,
                           const float* __restrict__ tbox,
                           float* __restrict__ C)
{
    const int tid = threadIdx.x;
    const int base_bq = tile * QPB;
    const int mode = detect_mode_block((const unsigned int*)ids);

    const float4* tb4 = (const float4*)tbox;
    for (int x = tid; x < NT; x += 128) sh->tb[x] = tb4[x];
    if (mode) {
        const long long* id64 = (const long long*)ids;
        for (int x = tid; x < NT; x += 128) sh->id[x] = (int)id64[x];
    } else {
        const int* id32 = (const int*)ids;
        for (int x = tid; x < NT; x += 128) sh->id[x] = id32[x];
    }

    const int w = tid >> 5, lane = tid & 31;
    for (int r = w; r < QPB; r += 4) {
        int bq = base_bq + r;
        const float* lr = logits + (size_t)bq * NC;
        float x0 = lr[lane];
        float x1 = lr[lane + 32];
        float x2 = (lane + 64 < NC) ? lr[lane + 64] : -1e30f;
        float m = fmaxf(x0, fmaxf(x1, x2));
        for (int o = 16; o; o >>= 1) m = fmaxf(m, __shfl_xor_sync(~0u, m, o));
        float e0 = expf(x0 - m);
        float e1 = expf(x1 - m);
        float e2 = (lane + 64 < NC) ? expf(x2 - m) : 0.0f;
        float s = e0 + e1 + e2;
        for (int o = 16; o; o >>= 1) s += __shfl_xor_sync(~0u, s, o);
        float inv = 1.0f / s;
        sh->prob[r][lane]      = e0 * inv;
        sh->prob[r][lane + 32] = e1 * inv;
        if (lane + 64 < NC) sh->prob[r][lane + 64] = e2 * inv;
        if (lane < 4) sh->box[r][lane] = boxes[(size_t)bq * 4 + lane];
    }
    __syncthreads();

    for (int r = 0; r < QPB; r++) {
        const int bq = base_bq + r;
        const float pcx = sh->box[r][0], pcy = sh->box[r][1];
        const float pw  = sh->box[r][2], ph  = sh->box[r][3];
        const float px0 = pcx - pw * 0.5f, py0 = pcy - ph * 0.5f;
        const float px1 = pcx + pw * 0.5f, py1 = pcy + ph * 0.5f;
        const float pa  = (px1 - px0) * (py1 - py0);
        float* Crow = C + (size_t)bq * NT;
        for (int j = tid; j < NT; j += 128) {
            float4 t = sh->tb[j];
            float tx0 = t.x, ty0 = t.y, tx1 = t.z, ty1 = t.w;
            float tcx = (tx0 + tx1) * 0.5f, tcy = (ty0 + ty1) * 0.5f;
            float tw = tx1 - tx0, th = ty1 - ty0;
            float cbb = fabsf(pcx - tcx) + fabsf(pcy - tcy)
                      + fabsf(pw - tw) + fabsf(ph - th);
            float ta = tw * th;
            float ix0 = fmaxf(px0, tx0), iy0 = fmaxf(py0, ty0);
            float ix1 = fminf(px1, tx1), iy1 = fminf(py1, ty1);
            float iw = fmaxf(ix1 - ix0, 0.0f), ih = fmaxf(iy1 - iy0, 0.0f);
            float inter = iw * ih;
            float uni = pa + ta - inter;
            float iou = inter / uni;
            float ex0 = fminf(px0, tx0), ey0 = fminf(py0, ty0);
            float ex1 = fmaxf(px1, tx1), ey1 = fmaxf(py1, ty1);
            float cw = fmaxf(ex1 - ex0, 0.0f), ch = fmaxf(ey1 - ey0, 0.0f);
            float ca = cw * ch;
            float giou = iou - (ca - uni) / ca;
            Crow[j] = 5.0f * cbb - sh->prob[r][sh->id[j]] - 2.0f * giou;
        }
    }
}

// ---------------------------------------------------------------------------
// LSA role: winner-lane-direct SMEM publish (no shfl / no broadcast p LDS on
// the pre-barrier path); all candidate rows loaded post-barrier under the
// two-pass fp64 window. Reference-exact fp64 sequence.
// ---------------------------------------------------------------------------
__device__ void lsa_block(LsaSh* sh, int b, float* __restrict__ out)
{
    const int tid = threadIdx.x;
    const int w = tid >> 5, lane = tid & 31;
    const bool g1ok = (tid < 97);

    double v[8];
    int rowof[8];
    int colv[8];
#pragma unroll
    for (int k = 0; k < 8; k++) {
        v[k] = 0.0; rowof[k] = 0;
        colv[k] = (k < 4) ? (4 * tid + k) : (512 + 4 * tid + (k - 4));
    }

    for (int x = tid; x <= Q; x += 128) sh->p[x] = 0;
    if (tid <= TPB) sh->u[tid] = 0.0;

    if (tid == 0) {
        volatile int* dv = &g_done[b];
        while (*dv < QT) { }
    }
    __syncthreads();
    __threadfence();

    const float4* cb4 = g_ctr4 + b * (TPB * ROW_F4);

    float4 nxt0 = __ldg(&cb4[tid]);
    float4 nxt1 = g1ok ? __ldg(&cb4[128 + tid]) : make_float4(0.f,0.f,0.f,0.f);

    int par = 0;

    for (int i = 1; i <= TPB; i++) {
        if (tid == 0) sh->p[0] = i;
        double minv[8];
        unsigned long long em[8];
        unsigned usedm = 0;

        float rwf[8] = { nxt0.x, nxt0.y, nxt0.z, nxt0.w,
                         nxt1.x, nxt1.y, nxt1.z, nxt1.w };
        unsigned long long bestE = ~0ULL; int bestJ = Q + 2;
#pragma unroll
        for (int k = 0; k < 8; k++) {
            if (k < 4 || g1ok) {
                double cur = ((double)rwf[k] - 0.0) - v[k];
                minv[k] = cur; em[k] = enc64(cur); sh->way[colv[k] + 1] = 0;
                if (em[k] < bestE) { bestE = em[k]; bestJ = colv[k] + 1; }
            } else { minv[k] = 1e300; em[k] = ~0ULL; }
        }

        if (i < TPB) {
            nxt0 = __ldg(&cb4[i * ROW_F4 + tid]);
            if (g1ok) nxt1 = __ldg(&cb4[i * ROW_F4 + 128 + tid]);
        }

        while (true) {
            // ---- warp argmin; the winning lane alone reads p and publishes ----
            unsigned hi  = (unsigned)(bestE >> 32);
            unsigned mhi = __reduce_min_sync(0xffffffffu, hi);
            unsigned bal = __ballot_sync(0xffffffffu, hi == mhi);
            if (__popc(bal) == 1) {
                int src = __ffs(bal) - 1;
                if (lane == src) {
                    sh->s_em[par][w] = bestE;
                    sh->s_j[par][w]  = bestJ;
                    sh->s_p[par][w]  = sh->p[bestJ];
                }
            } else {
                unsigned lo  = (hi == mhi) ? (unsigned)bestE : 0xffffffffu;
                unsigned mlo = __reduce_min_sync(0xffffffffu, lo);
                unsigned cjj = (hi == mhi && (unsigned)bestE == mlo)
                               ? (unsigned)bestJ : 0x7fffffffu;
                unsigned mj  = __reduce_min_sync(0xffffffffu, cjj);
                // bestJ values are distinct across lanes -> unique writer
                if ((unsigned)bestJ == mj) {
                    sh->s_em[par][w] = ((unsigned long long)mhi << 32) | mlo;
                    sh->s_j[par][w]  = mj;
                    sh->s_p[par][w]  = sh->p[mj];
                }
            }
            __syncthreads();                                   // ONE barrier

            unsigned long long ce0 = sh->s_em[par][0], ce1 = sh->s_em[par][1],
                               ce2 = sh->s_em[par][2], ce3 = sh->s_em[par][3];
            int cj0 = sh->s_j[par][0], cj1 = sh->s_j[par][1],
                cj2 = sh->s_j[par][2], cj3 = sh->s_j[par][3];
            int cp0 = sh->s_p[par][0], cp1 = sh->s_p[par][1],
                cp2 = sh->s_p[par][2], cp3 = sh->s_p[par][3];

            // issue all candidate-row loads NOW; consumed only in pass 2
            float4 ra0, rb0, ra1, rb1, ra2, rb2, ra3, rb3;
            if (cp0) { const float4* cr = cb4 + (cp0 - 1) * ROW_F4;
                ra0 = __ldg(&cr[tid]); if (g1ok) rb0 = __ldg(&cr[128 + tid]); }
            if (cp1) { const float4* cr = cb4 + (cp1 - 1) * ROW_F4;
                ra1 = __ldg(&cr[tid]); if (g1ok) rb1 = __ldg(&cr[128 + tid]); }
            if (cp2) { const float4* cr = cb4 + (cp2 - 1) * ROW_F4;
                ra2 = __ldg(&cr[tid]); if (g1ok) rb2 = __ldg(&cr[128 + tid]); }
            if (cp3) { const float4* cr = cb4 + (cp3 - 1) * ROW_F4;
                ra3 = __ldg(&cr[tid]); if (g1ok) rb3 = __ldg(&cr[128 + tid]); }

            // tree 4-way reduce (ties -> smaller j); track winner warp
            unsigned long long eA = ce0; int jA = cj0, pA = cp0, wA = 0;
            if (ce1 < eA || (ce1 == eA && cj1 < jA)) { eA = ce1; jA = cj1; pA = cp1; wA = 1; }
            unsigned long long eB = ce2; int jB = cj2, pB = cp2, wB = 2;
            if (ce3 < eB || (ce3 == eB && cj3 < jB)) { eB = ce3; jB = cj3; pB = cp3; wB = 3; }
            unsigned long long de = eA; int j1 = jA, i1 = pA, ww = wA;
            if (eB < de || (eB == de && jB < j1)) { de = eB; j1 = jB; i1 = pB; ww = wB; }
            const double delta = dec64(de);

            if (i1 == 0) {
#pragma unroll
                for (int k = 0; k < 8; k++) {
                    if ((k < 4 || g1ok) && ((usedm >> k) & 1u)) {
                        v[k] -= delta; sh->u[rowof[k]] += delta;
                    }
                }
                if (tid == 0) {
                    sh->u[i] += delta;
                    int jj = j1;
                    while (jj) { int jp = sh->way[jj]; sh->p[jj] = sh->p[jp]; jj = jp; }
                }
                par ^= 1;
                break;
            }

            // u[i1] read here: LDS latency hides under pass1 fp64.
            // Safe: row i1 receives no u update this iteration, and i1 != i.
            const double ui1 = sh->u[i1];

            // winner row registers
            float4 wa = ra0, wb = rb0;
            if (ww == 1) { wa = ra1; wb = rb1; }
            if (ww == 2) { wa = ra2; wb = rb2; }
            if (ww == 3) { wa = ra3; wb = rb3; }
            rwf[0] = wa.x; rwf[1] = wa.y; rwf[2] = wa.z; rwf[3] = wa.w;
            rwf[4] = wb.x; rwf[5] = wb.y; rwf[6] = wb.z; rwf[7] = wb.w;

            // t1 = (c - u[i1]) : independent of delta/v, runs parallel to pass1
            double t1[8];
#pragma unroll
            for (int k = 0; k < 8; k++) t1[k] = (double)rwf[k] - ui1;

            // ---- PASS 1: dual updates + m2 (reference order) ----
#pragma unroll
            for (int k = 0; k < 8; k++) {
                if (k < 4 || g1ok) {
                    if ((usedm >> k) & 1u) {
                        v[k] -= delta; sh->u[rowof[k]] += delta;
                    } else if (colv[k] + 1 != j1) {
                        minv[k] -= delta;
                        em[k] = enc64(minv[k]);
                    }
                }
            }
            if (tid == 0) sh->u[i] += delta;

            // ---- PASS 2: cur = t1 - v, merge vs m2, tree best-tracking ----
            unsigned long long be[8]; int bj[8];
#pragma unroll
            for (int k = 0; k < 8; k++) {
                bool act = (k < 4 || g1ok) && !((usedm >> k) & 1u)
                           && (colv[k] + 1 != j1);
                bj[k] = colv[k] + 1;
                if (act) {
                    double cur = t1[k] - v[k];
                    unsigned long long ec = enc64(cur);
                    if (ec < em[k]) { minv[k] = cur; em[k] = ec; sh->way[bj[k]] = j1; }
                    be[k] = em[k];
                } else {
                    be[k] = ~0ULL;
                }
            }
            // depth-3 tree (ties -> smaller j; per-thread colv ascending in k)
#pragma unroll
            for (int s = 1; s < 8; s <<= 1) {
#pragma unroll
                for (int k = 0; k < 8; k += 2 * s) {
                    if (be[k + s] < be[k] ||
                        (be[k + s] == be[k] && bj[k + s] < bj[k])) {
                        be[k] = be[k + s]; bj[k] = bj[k + s];
                    }
                }
            }
            bestE = be[0]; bestJ = bj[0];

            {
                int c = j1 - 1, og, okk;
                if (c < 512) { og = c >> 2;        okk = c & 3; }
                else         { og = (c - 512) >> 2; okk = 4 + ((c - 512) & 3); }
                if (og == tid) { usedm |= 1u << okk; rowof[okk] = i1; }
            }
            par ^= 1;
        }
        __syncthreads();
    }

#pragma unroll
    for (int k = 0; k < 8; k++) {
        if (k < 4 || g1ok) {
            int j = colv[k] + 1;
            if (sh->p[j] > 0) sh->ans[sh->p[j] - 1] = j - 1;
        }
    }
    __syncthreads();
    if (tid < TPB) {
        int a = sh->ans[tid];
        int rank = 0;
        for (int t2 = 0; t2 < TPB; t2++) rank += (sh->ans[t2] < a) ? 1 : 0;
        out[(size_t)C_ELEMS + (size_t)b * TPB + rank]                    = (float)a;
        out[(size_t)C_ELEMS + (size_t)BS * TPB + (size_t)b * TPB + rank] = (float)tid;
    }
    __syncthreads();
    if (tid == 0) atomicSub(&g_done[b], QT);   // restore 0 for next replay
}

// ---------------------------------------------------------------------------
__global__ void __launch_bounds__(128, 1) mega_kernel(
    const float* __restrict__ logits,
    const float* __restrict__ boxes,
    const void*  __restrict__ ids,
    const float* __restrict__ tbox,
    float* __restrict__ out)
{
    __shared__ AllSh sh;
    const int bid = blockIdx.x;
    if (bid < BS) {
        lsa_block(&sh.l, bid, out);
    } else if (bid < COST_OFF) {
        int sidx = bid - BS;
        slice_block(&sh.s, sidx & 15, sidx >> 4, logits, boxes, ids, tbox);
    } else {
        cost_block(&sh.c, bid - COST_OFF, logits, boxes, ids, tbox, out);
    }
}

// ---------------------------------------------------------------------------
extern "C" void kernel_launch(void* const* d_in, const int* in_sizes, int n_in,
                              void* d_out, int out_size)
{
    const float* logits = (const float*)d_in[0];
    const float* boxes  = (const float*)d_in[1];
    const void*  ids    = d_in[2];
    const float* tbox   = (const float*)d_in[3];
    float* out = (float*)d_out;

    mega_kernel<<<TOTAL_BLOCKS, 128>>>(logits, boxes, ids, tbox, out);
}

// round 15
// speedup vs baseline: 1.5568x; 1.0150x over previous
#include <cuda_runtime.h>
#include <cuda_bf16.h>
#include <math.h>

#define BS 16
#define Q 900
#define NC 92
#define TPB 100
#define NT 1600
#define C_ELEMS (16*900*1600)
#define ROW_F4 (Q/4)             // 225 float4 per row
#define QPB 8
#define QT 113                   // ceil(900/8) query tiles per batch
#define SLICE_BLOCKS (QT*BS)     // 1808
#define COST_OFF (BS + SLICE_BLOCKS)          // 1824
#define TOTAL_BLOCKS (COST_OFF + (BS*Q)/QPB)  // 3624
#define NTHR 256

__device__ float4 g_ctr4[BS * TPB * ROW_F4];
__device__ int    g_done[BS];    // per-batch slice-completion counters (self-resetting)

// ---------------------------------------------------------------------------
__device__ __forceinline__ int detect_mode_block(const unsigned int* __restrict__ ids)
{
    int ok = 1;
    for (int k = threadIdx.x; k < 800; k += NTHR) {
        unsigned lo = ids[2*k], hi = ids[2*k+1];
        if (hi != 0u || lo >= 92u) ok = 0;
    }
    return __syncthreads_and(ok);
}

// ---------------------------------------------------------------------------
struct LsaSh {
    double u[TPB + 4];
    int    p[Q + 8];
    int    way[Q + 8];
    unsigned long long s_em[2][8];
    int    s_j[2][8];
    int    s_p[2][8];
    int    ans[TPB];
};
struct SliceSh {
    float4 tb[TPB];
    int    id[TPB];
    float  prob[QPB][NC];
    float  box[QPB][4];
    float  outv[TPB][QPB];
};
struct CostSh {
    float4 tb[NT];
    int    id[NT];
    float  prob[QPB][NC];
    float  box[QPB][4];
};
union AllSh { LsaSh l; SliceSh s; CostSh c; };

// ---------------------------------------------------------------------------
__device__ __forceinline__ unsigned long long enc64(double x)
{
    long long b = __double_as_longlong(x);
    return (unsigned long long)(b ^ ((b >> 63) | 0x8000000000000000LL));
}
__device__ __forceinline__ double dec64(unsigned long long e)
{
    long long b = (long long)e;
    b ^= ((~b) >> 63) | 0x8000000000000000LL;
    return __longlong_as_double(b);
}

// ---------------------------------------------------------------------------
__device__ void slice_block(SliceSh* sh, int b, int qtile,
                            const float* __restrict__ logits,
                            const float* __restrict__ boxes,
                            const void*  __restrict__ ids,
                            const float* __restrict__ tbox)
{
    const int tid = threadIdx.x;
    const int w = tid >> 5, lane = tid & 31;
    const int q0 = qtile * QPB;
    const int mode = detect_mode_block((const unsigned int*)ids);

    const float4* tb4 = (const float4*)tbox;
    if (tid < TPB) sh->tb[tid] = tb4[b * TPB + tid];
    if (mode) {
        const long long* id64 = (const long long*)ids;
        if (tid < TPB) sh->id[tid] = (int)id64[b * TPB + tid];
    } else {
        const int* id32 = (const int*)ids;
        if (tid < TPB) sh->id[tid] = id32[b * TPB + tid];
    }

    // 8 warps, one query each (same per-query warp butterfly as before)
    {
        int r = w;
        int q = q0 + r;
        if (r < QPB && q < Q) {
            const float* lr = logits + ((size_t)(b * Q + q)) * NC;
            float x0 = lr[lane];
            float x1 = lr[lane + 32];
            float x2 = (lane + 64 < NC) ? lr[lane + 64] : -1e30f;
            float m = fmaxf(x0, fmaxf(x1, x2));
            for (int o = 16; o; o >>= 1) m = fmaxf(m, __shfl_xor_sync(~0u, m, o));
            float e0 = expf(x0 - m);
            float e1 = expf(x1 - m);
            float e2 = (lane + 64 < NC) ? expf(x2 - m) : 0.0f;
            float s = e0 + e1 + e2;
            for (int o = 16; o; o >>= 1) s += __shfl_xor_sync(~0u, s, o);
            float inv = 1.0f / s;
            sh->prob[r][lane]      = e0 * inv;
            sh->prob[r][lane + 32] = e1 * inv;
            if (lane + 64 < NC) sh->prob[r][lane + 64] = e2 * inv;
            if (lane < 4) sh->box[r][lane] = boxes[((size_t)(b * Q + q)) * 4 + lane];
        }
    }
    __syncthreads();

    for (int r = 0; r < QPB; r++) {
        int q = q0 + r;
        if (q >= Q) break;
        const float pcx = sh->box[r][0], pcy = sh->box[r][1];
        const float pw  = sh->box[r][2], ph  = sh->box[r][3];
        const float px0 = pcx - pw * 0.5f, py0 = pcy - ph * 0.5f;
        const float px1 = pcx + pw * 0.5f, py1 = pcy + ph * 0.5f;
        const float pa  = (px1 - px0) * (py1 - py0);
        if (tid < TPB) {
            float4 t = sh->tb[tid];
            float tx0 = t.x, ty0 = t.y, tx1 = t.z, ty1 = t.w;
            float tcx = (tx0 + tx1) * 0.5f, tcy = (ty0 + ty1) * 0.5f;
            float tw = tx1 - tx0, th = ty1 - ty0;
            float cbb = fabsf(pcx - tcx) + fabsf(pcy - tcy)
                      + fabsf(pw - tw) + fabsf(ph - th);
            float ta = tw * th;
            float ix0 = fmaxf(px0, tx0), iy0 = fmaxf(py0, ty0);
            float ix1 = fminf(px1, tx1), iy1 = fminf(py1, ty1);
            float iw = fmaxf(ix1 - ix0, 0.0f), ih = fmaxf(iy1 - iy0, 0.0f);
            float inter = iw * ih;
            float uni = pa + ta - inter;
            float iou = inter / uni;
            float ex0 = fminf(px0, tx0), ey0 = fminf(py0, ty0);
            float ex1 = fmaxf(px1, tx1), ey1 = fmaxf(py1, ty1);
            float cw = fmaxf(ex1 - ex0, 0.0f), ch = fmaxf(ey1 - ey0, 0.0f);
            float ca = cw * ch;
            float giou = iou - (ca - uni) / ca;
            sh->outv[tid][r] = 5.0f * cbb - sh->prob[r][sh->id[tid]] - 2.0f * giou;
        }
    }
    __syncthreads();

    float* g_ctrf = (float*)g_ctr4;
    for (int idx = tid; idx < TPB * QPB; idx += NTHR) {
        int t = idx >> 3, r = idx & 7;
        int q = q0 + r;
        if (q < Q)
            g_ctrf[b * (TPB * Q) + t * Q + q] = sh->outv[t][r];
    }

    __syncthreads();
    __threadfence();
    if (tid == 0) atomicAdd(&g_done[b], 1);
}

// ---------------------------------------------------------------------------
__device__ void cost_block(CostSh* sh, int tile,
                           const float* __restrict__ logits,
                           const float* __restrict__ boxes,
                           const void*  __restrict__ ids,
                           const float* __restrict__ tbox,
                           float* __restrict__ C)
{
    const int tid = threadIdx.x;
    const int base_bq = tile * QPB;
    const int mode = detect_mode_block((const unsigned int*)ids);

    const float4* tb4 = (const float4*)tbox;
    for (int x = tid; x < NT; x += NTHR) sh->tb[x] = tb4[x];
    if (mode) {
        const long long* id64 = (const long long*)ids;
        for (int x = tid; x < NT; x += NTHR) sh->id[x] = (int)id64[x];
    } else {
        const int* id32 = (const int*)ids;
        for (int x = tid; x < NT; x += NTHR) sh->id[x] = id32[x];
    }

    const int w = tid >> 5, lane = tid & 31;
    {
        int r = w;
        if (r < QPB) {
            int bq = base_bq + r;
            const float* lr = logits + (size_t)bq * NC;
            float x0 = lr[lane];
            float x1 = lr[lane + 32];
            float x2 = (lane + 64 < NC) ? lr[lane + 64] : -1e30f;
            float m = fmaxf(x0, fmaxf(x1, x2));
            for (int o = 16; o; o >>= 1) m = fmaxf(m, __shfl_xor_sync(~0u, m, o));
            float e0 = expf(x0 - m);
            float e1 = expf(x1 - m);
            float e2 = (lane + 64 < NC) ? expf(x2 - m) : 0.0f;
            float s = e0 + e1 + e2;
            for (int o = 16; o; o >>= 1) s += __shfl_xor_sync(~0u, s, o);
            float inv = 1.0f / s;
            sh->prob[r][lane]      = e0 * inv;
            sh->prob[r][lane + 32] = e1 * inv;
            if (lane + 64 < NC) sh->prob[r][lane + 64] = e2 * inv;
            if (lane < 4) sh->box[r][lane] = boxes[(size_t)bq * 4 + lane];
        }
    }
    __syncthreads();

    for (int r = 0; r < QPB; r++) {
        const int bq = base_bq + r;
        const float pcx = sh->box[r][0], pcy = sh->box[r][1];
        const float pw  = sh->box[r][2], ph  = sh->box[r][3];
        const float px0 = pcx - pw * 0.5f, py0 = pcy - ph * 0.5f;
        const float px1 = pcx + pw * 0.5f, py1 = pcy + ph * 0.5f;
        const float pa  = (px1 - px0) * (py1 - py0);
        float* Crow = C + (size_t)bq * NT;
        for (int j = tid; j < NT; j += NTHR) {
            float4 t = sh->tb[j];
            float tx0 = t.x, ty0 = t.y, tx1 = t.z, ty1 = t.w;
            float tcx = (tx0 + tx1) * 0.5f, tcy = (ty0 + ty1) * 0.5f;
            float tw = tx1 - tx0, th = ty1 - ty0;
            float cbb = fabsf(pcx - tcx) + fabsf(pcy - tcy)
                      + fabsf(pw - tw) + fabsf(ph - th);
            float ta = tw * th;
            float ix0 = fmaxf(px0, tx0), iy0 = fmaxf(py0, ty0);
            float ix1 = fminf(px1, tx1), iy1 = fminf(py1, ty1);
            float iw = fmaxf(ix1 - ix0, 0.0f), ih = fmaxf(iy1 - iy0, 0.0f);
            float inter = iw * ih;
            float uni = pa + ta - inter;
            float iou = inter / uni;
            float ex0 = fminf(px0, tx0), ey0 = fminf(py0, ty0);
            float ex1 = fmaxf(px1, tx1), ey1 = fmaxf(py1, ty1);
            float cw = fmaxf(ex1 - ex0, 0.0f), ch = fmaxf(ey1 - ey0, 0.0f);
            float ca = cw * ch;
            float giou = iou - (ca - uni) / ca;
            Crow[j] = 5.0f * cbb - sh->prob[r][sh->id[j]] - 2.0f * giou;
        }
    }
}

// ---------------------------------------------------------------------------
// LSA role, 256 threads: 4 columns/thread (tid < 225), one float4 per row.
// Winner-lane-direct publish; candidate rows (8 slots x 1 float4) loaded
// post-barrier under the fp64 window; cur/ec hoisted before pass1.
// Reference-exact fp64 sequence.
// ---------------------------------------------------------------------------
__device__ void lsa_block(LsaSh* sh, int b, float* __restrict__ out)
{
    const int tid = threadIdx.x;
    const int w = tid >> 5, lane = tid & 31;
    const bool act = (tid < ROW_F4);           // 225 active threads

    double v[4];
    int rowof[4];
#pragma unroll
    for (int k = 0; k < 4; k++) { v[k] = 0.0; rowof[k] = 0; }
    const int col0 = 4 * tid;                  // colv[k] = col0 + k

    for (int x = tid; x <= Q; x += NTHR) sh->p[x] = 0;
    if (tid <= TPB) sh->u[tid] = 0.0;

    if (tid == 0) {
        volatile int* dv = &g_done[b];
        while (*dv < QT) { }
    }
    __syncthreads();
    __threadfence();

    const float4* cb4 = g_ctr4 + b * (TPB * ROW_F4);

    float4 nxt0 = act ? __ldg(&cb4[tid]) : make_float4(0.f,0.f,0.f,0.f);

    int par = 0;

    for (int i = 1; i <= TPB; i++) {
        if (tid == 0) sh->p[0] = i;
        double minv[4];
        unsigned long long em[4];
        unsigned usedm = 0;

        float rwf[4] = { nxt0.x, nxt0.y, nxt0.z, nxt0.w };
        unsigned long long bestE = ~0ULL; int bestJ = Q + 2;
#pragma unroll
        for (int k = 0; k < 4; k++) {
            if (act) {
                double cur = ((double)rwf[k] - 0.0) - v[k];
                minv[k] = cur; em[k] = enc64(cur); sh->way[col0 + k + 1] = 0;
                if (em[k] < bestE) { bestE = em[k]; bestJ = col0 + k + 1; }
            } else { minv[k] = 1e300; em[k] = ~0ULL; }
        }

        if (i < TPB && act) nxt0 = __ldg(&cb4[i * ROW_F4 + tid]);

        while (true) {
            // ---- warp argmin; the winning lane alone reads p and publishes ----
            unsigned hi  = (unsigned)(bestE >> 32);
            unsigned mhi = __reduce_min_sync(0xffffffffu, hi);
            unsigned bal = __ballot_sync(0xffffffffu, hi == mhi);
            if (__popc(bal) == 1) {
                int src = __ffs(bal) - 1;
                if (lane == src) {
                    sh->s_em[par][w] = bestE;
                    sh->s_j[par][w]  = bestJ;
                    sh->s_p[par][w]  = sh->p[bestJ];
                }
            } else {
                unsigned lo  = (hi == mhi) ? (unsigned)bestE : 0xffffffffu;
                unsigned mlo = __reduce_min_sync(0xffffffffu, lo);
                unsigned cjj = (hi == mhi && (unsigned)bestE == mlo)
                               ? (unsigned)bestJ : 0x7fffffffu;
                unsigned mj  = __reduce_min_sync(0xffffffffu, cjj);
                if ((unsigned)bestJ == mj) {
                    sh->s_em[par][w] = ((unsigned long long)mhi << 32) | mlo;
                    sh->s_j[par][w]  = mj;
                    sh->s_p[par][w]  = sh->p[mj];
                }
            }
            __syncthreads();                                   // ONE barrier

            unsigned long long ce[8]; int cj[8], cp[8], ci[8];
#pragma unroll
            for (int s = 0; s < 8; s++) {
                ce[s] = sh->s_em[par][s];
                cj[s] = sh->s_j[par][s];
                cp[s] = sh->s_p[par][s];
                ci[s] = s;
            }

            // issue all 8 candidate-row loads NOW (1 float4 each)
            float4 ra[8];
#pragma unroll
            for (int s = 0; s < 8; s++) {
                if (cp[s] && act)
                    ra[s] = __ldg(&cb4[(cp[s] - 1) * ROW_F4 + tid]);
            }

            // depth-3 tree reduce (ties -> smaller j), track winner slot
#pragma unroll
            for (int st = 1; st < 8; st <<= 1) {
#pragma unroll
                for (int k = 0; k < 8; k += 2 * st) {
                    if (ce[k + st] < ce[k] ||
                        (ce[k + st] == ce[k] && cj[k + st] < cj[k])) {
                        ce[k] = ce[k + st]; cj[k] = cj[k + st];
                        cp[k] = cp[k + st]; ci[k] = ci[k + st];
                    }
                }
            }
            const unsigned long long de = ce[0];
            const int j1 = cj[0], i1 = cp[0], ww = ci[0];
            const double delta = dec64(de);

            if (i1 == 0) {
#pragma unroll
                for (int k = 0; k < 4; k++) {
                    if (act && ((usedm >> k) & 1u)) {
                        v[k] -= delta; sh->u[rowof[k]] += delta;
                    }
                }
                if (tid == 0) {
                    sh->u[i] += delta;
                    int jj = j1;
                    while (jj) { int jp = sh->way[jj]; sh->p[jj] = sh->p[jp]; jj = jp; }
                }
                par ^= 1;
                break;
            }

            // u[i1]: safe unordered read (row i1 gets no u update this iter)
            const double ui1 = sh->u[i1];

            // winner row registers (8-way select)
            float4 wsel = ra[0];
#pragma unroll
            for (int s = 1; s < 8; s++) if (ww == s) wsel = ra[s];
            rwf[0] = wsel.x; rwf[1] = wsel.y; rwf[2] = wsel.z; rwf[3] = wsel.w;

            // cur/ec hoisted BEFORE pass1 (v of unused cols unchanged by the
            // update; used cols never consume cur)
            double curv[4]; unsigned long long ec[4];
#pragma unroll
            for (int k = 0; k < 4; k++) {
                double t1 = (double)rwf[k] - ui1;
                curv[k] = t1 - v[k];
                ec[k] = enc64(curv[k]);
            }

            // ---- PASS 1: dual updates + m2 (reference order) ----
#pragma unroll
            for (int k = 0; k < 4; k++) {
                if (act) {
                    if ((usedm >> k) & 1u) {
                        v[k] -= delta; sh->u[rowof[k]] += delta;
                    } else if (col0 + k + 1 != j1) {
                        minv[k] -= delta;
                        em[k] = enc64(minv[k]);
                    }
                }
            }
            if (tid == 0) sh->u[i] += delta;

            // ---- PASS 2: merge cur vs m2, tree best-tracking ----
            unsigned long long be[4]; int bj[4];
#pragma unroll
            for (int k = 0; k < 4; k++) {
                bool a2 = act && !((usedm >> k) & 1u) && (col0 + k + 1 != j1);
                bj[k] = col0 + k + 1;
                if (a2) {
                    if (ec[k] < em[k]) { minv[k] = curv[k]; em[k] = ec[k]; sh->way[bj[k]] = j1; }
                    be[k] = em[k];
                } else {
                    be[k] = ~0ULL;
                }
            }
#pragma unroll
            for (int s = 1; s < 4; s <<= 1) {
#pragma unroll
                for (int k = 0; k < 4; k += 2 * s) {
                    if (be[k + s] < be[k] ||
                        (be[k + s] == be[k] && bj[k + s] < bj[k])) {
                        be[k] = be[k + s]; bj[k] = bj[k + s];
                    }
                }
            }
            bestE = be[0]; bestJ = bj[0];

            {
                int c = j1 - 1;
                if ((c >> 2) == tid) { usedm |= 1u << (c & 3); rowof[c & 3] = i1; }
            }
            par ^= 1;
        }
        __syncthreads();
    }

#pragma unroll
    for (int k = 0; k < 4; k++) {
        if (act) {
            int j = col0 + k + 1;
            if (sh->p[j] > 0) sh->ans[sh->p[j] - 1] = j - 1;
        }
    }
    __syncthreads();
    if (tid < TPB) {
        int a = sh->ans[tid];
        int rank = 0;
        for (int t2 = 0; t2 < TPB; t2++) rank += (sh->ans[t2] < a) ? 1 : 0;
        out[(size_t)C_ELEMS + (size_t)b * TPB + rank]                    = (float)a;
        out[(size_t)C_ELEMS + (size_t)BS * TPB + (size_t)b * TPB + rank] = (float)tid;
    }
    __syncthreads();
    if (tid == 0) atomicSub(&g_done[b], QT);   // restore 0 for next replay
}

// ---------------------------------------------------------------------------
__global__ void __launch_bounds__(NTHR, 1) mega_kernel(
    const float* __restrict__ logits,
    const float* __restrict__ boxes,
    const void*  __restrict__ ids,
    const float* __restrict__ tbox,
    float* __restrict__ out)
{
    __shared__ AllSh sh;
    const int bid = blockIdx.x;
    if (bid < BS) {
        lsa_block(&sh.l, bid, out);
    } else if (bid < COST_OFF) {
        int sidx = bid - BS;
        slice_block(&sh.s, sidx & 15, sidx >> 4, logits, boxes, ids, tbox);
    } else {
        cost_block(&sh.c, bid - COST_OFF, logits, boxes, ids, tbox, out);
    }
}

// ---------------------------------------------------------------------------
extern "C" void kernel_launch(void* const* d_in, const int* in_sizes, int n_in,
                              void* d_out, int out_size)
{
    const float* logits = (const float*)d_in[0];
    const float* boxes  = (const float*)d_in[1];
    const void*  ids    = d_in[2];
    const float* tbox   = (const float*)d_in[3];
    float* out = (float*)d_out;

    mega_kernel<<<TOTAL_BLOCKS, NTHR>>>(logits, boxes, ids, tbox, out);
}